// round 4
// baseline (speedup 1.0000x reference)
#include <cuda_runtime.h>

#define TSEQ 2048
#define BB 2
#define DM 1024
#define NH 16
#define HD 64
#define MR (BB*TSEQ)   // 4096 rows

// Scratch (allocation-free rule: __device__ globals)
__device__ float g_q[(size_t)MR * DM];
__device__ float g_k[(size_t)MR * DM];
__device__ float g_v[(size_t)MR * DM];
__device__ float g_att[(size_t)MR * DM];

// ---------------------------------------------------------------------------
// Y[m,n] = sum_k X[m,k] * W[n,k]   (x @ W^T, both row-major K-contiguous)
// M = 4096 (blockIdx.y*128), N = 1024 (blockIdx.x*128), K = 1024
// 128x128 tile, BK=16, 256 threads, 8x8 per-thread register tile.
// Global->register prefetch double buffering across k-panels.
// ---------------------------------------------------------------------------
__device__ __forceinline__ void sgemm_body(const float* __restrict__ X,
                                           const float* __restrict__ W,
                                           float* __restrict__ Y)
{
    const int K = DM, N = DM;
    __shared__ float As[16][132];
    __shared__ float Bs[16][132];
    const int tid = threadIdx.x;
    const int tx = tid & 15, ty = tid >> 4;
    const float* Xp = X + (size_t)(blockIdx.y * 128) * K;
    const float* Wp = W + (size_t)(blockIdx.x * 128) * K;
    const int lr = tid >> 2;          // 0..63
    const int lc = (tid & 3) << 2;    // 0,4,8,12

    float acc[8][8];
#pragma unroll
    for (int i = 0; i < 8; i++)
#pragma unroll
        for (int j = 0; j < 8; j++) acc[i][j] = 0.f;

    // Prologue: fetch panel 0 into registers.
    float4 pa[2], pb[2];
#pragma unroll
    for (int i = 0; i < 2; i++) {
        const int r = lr + i * 64;
        pa[i] = *(const float4*)(Xp + (size_t)r * K + lc);
        pb[i] = *(const float4*)(Wp + (size_t)r * K + lc);
    }

    for (int k0 = 0; k0 < K; k0 += 16) {
        // Commit prefetched panel to smem.
#pragma unroll
        for (int i = 0; i < 2; i++) {
            const int r = lr + i * 64;
            As[lc + 0][r] = pa[i].x; As[lc + 1][r] = pa[i].y;
            As[lc + 2][r] = pa[i].z; As[lc + 3][r] = pa[i].w;
            Bs[lc + 0][r] = pb[i].x; Bs[lc + 1][r] = pb[i].y;
            Bs[lc + 2][r] = pb[i].z; Bs[lc + 3][r] = pb[i].w;
        }
        __syncthreads();

        // Prefetch next panel (overlaps with compute below).
        if (k0 + 16 < K) {
#pragma unroll
            for (int i = 0; i < 2; i++) {
                const int r = lr + i * 64;
                pa[i] = *(const float4*)(Xp + (size_t)r * K + k0 + 16 + lc);
                pb[i] = *(const float4*)(Wp + (size_t)r * K + k0 + 16 + lc);
            }
        }

#pragma unroll
        for (int k = 0; k < 16; k++) {
            float a[8], b[8];
            *(float4*)(a)     = *(const float4*)&As[k][ty * 8];
            *(float4*)(a + 4) = *(const float4*)&As[k][ty * 8 + 4];
            *(float4*)(b)     = *(const float4*)&Bs[k][tx * 8];
            *(float4*)(b + 4) = *(const float4*)&Bs[k][tx * 8 + 4];
#pragma unroll
            for (int i = 0; i < 8; i++)
#pragma unroll
                for (int j = 0; j < 8; j++)
                    acc[i][j] = fmaf(a[i], b[j], acc[i][j]);
        }
        __syncthreads();
    }

    float* Yp = Y + (size_t)(blockIdx.y * 128 + ty * 8) * N + blockIdx.x * 128 + tx * 8;
#pragma unroll
    for (int i = 0; i < 8; i++) {
        *(float4*)(Yp + (size_t)i * N)     = make_float4(acc[i][0], acc[i][1], acc[i][2], acc[i][3]);
        *(float4*)(Yp + (size_t)i * N + 4) = make_float4(acc[i][4], acc[i][5], acc[i][6], acc[i][7]);
    }
}

__global__ __launch_bounds__(256) void qkv_kernel(const float* __restrict__ x,
                                                  const float* __restrict__ Wq,
                                                  const float* __restrict__ Wk,
                                                  const float* __restrict__ Wv)
{
    const float* W = (blockIdx.z == 0) ? Wq : ((blockIdx.z == 1) ? Wk : Wv);
    float* Y       = (blockIdx.z == 0) ? g_q : ((blockIdx.z == 1) ? g_k : g_v);
    sgemm_body(x, W, Y);
}

__global__ __launch_bounds__(256) void proj_kernel(const float* __restrict__ Wo,
                                                   float* __restrict__ out)
{
    sgemm_body(g_att, Wo, out);
}

// ---------------------------------------------------------------------------
// Flash attention, causal. Grid: (T/64, H, B). Block: 64 threads.
// One thread per query row; Q row + O accumulator in registers.
// K/V staged in smem in 64-key tiles; two-phase online softmax per tile.
// Unrolls capped at 8 to bound code size / ptxas time.
// ---------------------------------------------------------------------------
__global__ __launch_bounds__(64) void attn_kernel()
{
    __shared__ float Ks[64][64];   // 16 KB
    __shared__ float Vs[64][64];   // 16 KB
    __shared__ float Sb[64][64];   // 16 KB  (indexed [kk][tid] -> conflict-free)

    const int tid = threadIdx.x;
    const int q0  = blockIdx.x * 64;
    const int h   = blockIdx.y;
    const int b   = blockIdx.z;
    const int qi  = q0 + tid;
    const size_t qoff = (size_t)(b * TSEQ + qi) * DM + h * HD;

    float qreg[64], O[64];
#pragma unroll
    for (int d = 0; d < 64; d += 4) {
        float4 v = *(const float4*)(g_q + qoff + d);
        qreg[d] = v.x; qreg[d + 1] = v.y; qreg[d + 2] = v.z; qreg[d + 3] = v.w;
    }
#pragma unroll 8
    for (int d = 0; d < 64; d++) O[d] = 0.f;

    float m = -1e30f, l = 0.f;
    const int ntiles = (q0 >> 6) + 1;

    for (int t = 0; t < ntiles; t++) {
        // Coalesced K/V tile load: thread tid owns column tid across all 64 rows.
        const size_t kbase = (size_t)(b * TSEQ + t * 64) * DM + h * HD + tid;
#pragma unroll 8
        for (int r = 0; r < 64; r++) {
            Ks[r][tid] = g_k[kbase + (size_t)r * DM];
            Vs[r][tid] = g_v[kbase + (size_t)r * DM];
        }
        __syncthreads();

        // Phase A: scores for this tile + tile max.
        const int klim = qi - t * 64;   // kk > klim => future key => masked
        float tmax = -1e30f;
#pragma unroll 2
        for (int kk = 0; kk < 64; kk++) {
            float s0 = 0.f, s1 = 0.f, s2 = 0.f, s3 = 0.f;
#pragma unroll
            for (int d = 0; d < 64; d += 4) {
                float4 kv = *(const float4*)&Ks[kk][d];
                s0 = fmaf(qreg[d],     kv.x, s0);
                s1 = fmaf(qreg[d + 1], kv.y, s1);
                s2 = fmaf(qreg[d + 2], kv.z, s2);
                s3 = fmaf(qreg[d + 3], kv.w, s3);
            }
            float s = ((s0 + s1) + (s2 + s3)) * 0.125f;  // 1/sqrt(64)
            if (kk > klim) s = -1e30f;
            Sb[kk][tid] = s;
            tmax = fmaxf(tmax, s);
        }

        // Single rescale per tile.
        const float mnew = fmaxf(m, tmax);
        const float corr = __expf(m - mnew);
        l *= corr;
#pragma unroll 8
        for (int d = 0; d < 64; d++) O[d] *= corr;
        m = mnew;

        // Phase B: probabilities + PV accumulate.
#pragma unroll 2
        for (int kk = 0; kk < 64; kk++) {
            const float p = __expf(Sb[kk][tid] - m);
            l += p;
#pragma unroll
            for (int d = 0; d < 64; d += 4) {
                float4 vv = *(const float4*)&Vs[kk][d];
                O[d]     = fmaf(p, vv.x, O[d]);
                O[d + 1] = fmaf(p, vv.y, O[d + 1]);
                O[d + 2] = fmaf(p, vv.z, O[d + 2]);
                O[d + 3] = fmaf(p, vv.w, O[d + 3]);
            }
        }
        __syncthreads();
    }

    const float inv = 1.f / l;
    float* op = g_att + qoff;
#pragma unroll
    for (int d = 0; d < 64; d += 4) {
        *(float4*)(op + d) = make_float4(O[d] * inv, O[d + 1] * inv,
                                         O[d + 2] * inv, O[d + 3] * inv);
    }
}

// ---------------------------------------------------------------------------
extern "C" void kernel_launch(void* const* d_in, const int* in_sizes, int n_in,
                              void* d_out, int out_size)
{
    const float* x  = (const float*)d_in[0];
    const float* Wq = (const float*)d_in[1];
    const float* Wk = (const float*)d_in[2];
    const float* Wv = (const float*)d_in[3];
    const float* Wo = (const float*)d_in[4];
    float* out = (float*)d_out;

    dim3 gq(DM / 128, MR / 128, 3);
    qkv_kernel<<<gq, 256>>>(x, Wq, Wk, Wv);

    dim3 ga(TSEQ / 64, NH, BB);
    attn_kernel<<<ga, 64>>>();

    dim3 gp(DM / 128, MR / 128, 1);
    proj_kernel<<<gp, 256>>>(Wo, out);
}

// round 5
// speedup vs baseline: 1.5688x; 1.5688x over previous
#include <cuda_runtime.h>

#define TSEQ 2048
#define BB 2
#define DM 1024
#define NH 16
#define HD 64
#define MR (BB*TSEQ)   // 4096 rows

typedef unsigned long long ull;

// Scratch (allocation-free rule: __device__ globals)
__device__ float g_q[(size_t)MR * DM];
__device__ float g_k[(size_t)MR * DM];
__device__ float g_v[(size_t)MR * DM];
__device__ float g_att[(size_t)MR * DM];

// ---- packed fp32x2 helpers (Blackwell FFMA2 path) -------------------------
__device__ __forceinline__ ull ffma2(ull a, ull b, ull c) {
    ull d;
    asm("fma.rn.f32x2 %0, %1, %2, %3;" : "=l"(d) : "l"(a), "l"(b), "l"(c));
    return d;
}
__device__ __forceinline__ ull pack2dup(float x) {
    ull r;
    asm("mov.b64 %0, {%1, %1};" : "=l"(r) : "f"(x));
    return r;
}

// ---------------------------------------------------------------------------
// Y[m,n] = sum_k X[m,k] * W[n,k]   (x @ W^T)
// 128x128 tile, BK=16, 256 threads, 8x8 per-thread tile via f32x2 FFMA2.
// ---------------------------------------------------------------------------
__device__ __forceinline__ void sgemm_body(const float* __restrict__ X,
                                           const float* __restrict__ W,
                                           float* __restrict__ Y)
{
    const int K = DM, N = DM;
    __shared__ float As[16][132];
    __shared__ float Bs[16][132];
    const int tid = threadIdx.x;
    const int tx = tid & 15, ty = tid >> 4;
    const float* Xp = X + (size_t)(blockIdx.y * 128) * K;
    const float* Wp = W + (size_t)(blockIdx.x * 128) * K;
    const int lr = tid >> 2;          // 0..63
    const int lc = (tid & 3) << 2;    // 0,4,8,12

    ull acc2[8][4];
#pragma unroll
    for (int i = 0; i < 8; i++)
#pragma unroll
        for (int j = 0; j < 4; j++) acc2[i][j] = 0ull;

    // Prologue: fetch panel 0 into registers.
    float4 pa[2], pb[2];
#pragma unroll
    for (int i = 0; i < 2; i++) {
        const int r = lr + i * 64;
        pa[i] = *(const float4*)(Xp + (size_t)r * K + lc);
        pb[i] = *(const float4*)(Wp + (size_t)r * K + lc);
    }

    for (int k0 = 0; k0 < K; k0 += 16) {
#pragma unroll
        for (int i = 0; i < 2; i++) {
            const int r = lr + i * 64;
            As[lc + 0][r] = pa[i].x; As[lc + 1][r] = pa[i].y;
            As[lc + 2][r] = pa[i].z; As[lc + 3][r] = pa[i].w;
            Bs[lc + 0][r] = pb[i].x; Bs[lc + 1][r] = pb[i].y;
            Bs[lc + 2][r] = pb[i].z; Bs[lc + 3][r] = pb[i].w;
        }
        __syncthreads();

        if (k0 + 16 < K) {
#pragma unroll
            for (int i = 0; i < 2; i++) {
                const int r = lr + i * 64;
                pa[i] = *(const float4*)(Xp + (size_t)r * K + k0 + 16 + lc);
                pb[i] = *(const float4*)(Wp + (size_t)r * K + k0 + 16 + lc);
            }
        }

#pragma unroll
        for (int k = 0; k < 16; k++) {
            float a[8];
            *(float4*)(a)     = *(const float4*)&As[k][ty * 8];
            *(float4*)(a + 4) = *(const float4*)&As[k][ty * 8 + 4];
            // b pairs read directly as 64-bit lanes (low float = even column)
            ull b2[4];
            double2 bl0 = *(const double2*)&Bs[k][tx * 8];
            double2 bl1 = *(const double2*)&Bs[k][tx * 8 + 4];
            b2[0] = __double_as_longlong(bl0.x);
            b2[1] = __double_as_longlong(bl0.y);
            b2[2] = __double_as_longlong(bl1.x);
            b2[3] = __double_as_longlong(bl1.y);
#pragma unroll
            for (int i = 0; i < 8; i++) {
                const ull a2 = pack2dup(a[i]);
#pragma unroll
                for (int j = 0; j < 4; j++)
                    acc2[i][j] = ffma2(a2, b2[j], acc2[i][j]);
            }
        }
        __syncthreads();
    }

    float* Yp = Y + (size_t)(blockIdx.y * 128 + ty * 8) * N + blockIdx.x * 128 + tx * 8;
#pragma unroll
    for (int i = 0; i < 8; i++) {
        float2 f0 = *(float2*)&acc2[i][0];
        float2 f1 = *(float2*)&acc2[i][1];
        float2 f2 = *(float2*)&acc2[i][2];
        float2 f3 = *(float2*)&acc2[i][3];
        *(float4*)(Yp + (size_t)i * N)     = make_float4(f0.x, f0.y, f1.x, f1.y);
        *(float4*)(Yp + (size_t)i * N + 4) = make_float4(f2.x, f2.y, f3.x, f3.y);
    }
}

__global__ __launch_bounds__(256) void qkv_kernel(const float* __restrict__ x,
                                                  const float* __restrict__ Wq,
                                                  const float* __restrict__ Wk,
                                                  const float* __restrict__ Wv)
{
    const float* W = (blockIdx.z == 0) ? Wq : ((blockIdx.z == 1) ? Wk : Wv);
    float* Y       = (blockIdx.z == 0) ? g_q : ((blockIdx.z == 1) ? g_k : g_v);
    sgemm_body(x, W, Y);
}

__global__ __launch_bounds__(256) void proj_kernel(const float* __restrict__ Wo,
                                                   float* __restrict__ out)
{
    sgemm_body(g_att, Wo, out);
}

// ---------------------------------------------------------------------------
// Flash attention as two block-GEMMs per K-tile.
// Block: 256 threads. Q-tile = 128 queries, K-tile = 64 keys, D = 64.
// Thread (ty,tx): ty=tid/16, tx=tid%16.
//   GEMM-A: S[i][j], per-thread 8(i) x 4(j), j = tx + 16*jj (2-way max conflicts)
//   GEMM-B: O[i][dd], per-thread 8(i) x 4(dd), dd = tx*4 + c
// All smem tiles row-major with stride 68 (float4-aligned, bank-spread).
// ---------------------------------------------------------------------------
#define BQ  128
#define BKT 64
#define STR 68
#define ATT_SMEM ((BQ*STR + BKT*STR + BKT*STR + BQ*STR + 3*BQ) * 4)

__global__ __launch_bounds__(256) void attn_kernel()
{
    extern __shared__ float sm[];
    float* Qs = sm;                    // [128][68]
    float* Ks = Qs + BQ * STR;         // [64][68]
    float* Vs = Ks + BKT * STR;        // [64][68]
    float* Ps = Vs + BKT * STR;        // [128][68]
    float* mS = Ps + BQ * STR;         // [128]
    float* lS = mS + BQ;               // [128]
    float* cS = lS + BQ;               // [128]

    const int tid = threadIdx.x;
    const int tx = tid & 15;
    const int ty = tid >> 4;
    const int xb = gridDim.x - 1 - blockIdx.x;   // heavy blocks first
    const int q0 = xb * BQ;
    const int h  = blockIdx.y;
    const int b  = blockIdx.z;

    // Load Q tile (coalesced; conflict-free smem writes)
    const size_t qgbase = (size_t)(b * TSEQ + q0) * DM + h * HD;
    for (int idx = tid; idx < BQ * HD; idx += 256) {
        const int i = idx >> 6, d = idx & 63;
        Qs[i * STR + d] = g_q[qgbase + (size_t)i * DM + d];
    }
    if (tid < BQ) { mS[tid] = -1e30f; lS[tid] = 0.f; }

    float O[8][4];
#pragma unroll
    for (int i = 0; i < 8; i++)
#pragma unroll
        for (int c = 0; c < 4; c++) O[i][c] = 0.f;

    const int ntiles = 2 * (xb + 1);
    for (int t = 0; t < ntiles; t++) {
        __syncthreads();   // prev GEMM-B done with Ks/Vs/Ps

        // K/V tile load
        const size_t kg = (size_t)(b * TSEQ + t * BKT) * DM + h * HD;
        for (int idx = tid; idx < BKT * HD; idx += 256) {
            const int j = idx >> 6, d = idx & 63;
            Ks[j * STR + d] = g_k[kg + (size_t)j * DM + d];
            Vs[j * STR + d] = g_v[kg + (size_t)j * DM + d];
        }
        __syncthreads();

        // ---- GEMM-A: S = Q . K^T -------------------------------------
        float acc[8][4];
#pragma unroll
        for (int i = 0; i < 8; i++)
#pragma unroll
            for (int j = 0; j < 4; j++) acc[i][j] = 0.f;

#pragma unroll 2
        for (int d4 = 0; d4 < 16; d4++) {
#pragma unroll
            for (int hh = 0; hh < 2; hh++) {
                float4 qv[4];
#pragma unroll
                for (int r = 0; r < 4; r++)
                    qv[r] = *(const float4*)&Qs[(ty * 8 + hh * 4 + r) * STR + d4 * 4];
#pragma unroll
                for (int jj = 0; jj < 4; jj++) {
                    const float4 kv = *(const float4*)&Ks[(tx + 16 * jj) * STR + d4 * 4];
#pragma unroll
                    for (int r = 0; r < 4; r++) {
                        acc[hh * 4 + r][jj] = fmaf(qv[r].x, kv.x, acc[hh * 4 + r][jj]);
                        acc[hh * 4 + r][jj] = fmaf(qv[r].y, kv.y, acc[hh * 4 + r][jj]);
                        acc[hh * 4 + r][jj] = fmaf(qv[r].z, kv.z, acc[hh * 4 + r][jj]);
                        acc[hh * 4 + r][jj] = fmaf(qv[r].w, kv.w, acc[hh * 4 + r][jj]);
                    }
                }
            }
        }

        // Scale + causal mask, write S
#pragma unroll
        for (int ii = 0; ii < 8; ii++) {
            const int i = ty * 8 + ii;
#pragma unroll
            for (int jj = 0; jj < 4; jj++) {
                const int j = tx + 16 * jj;
                float s = acc[ii][jj] * 0.125f;
                if (t * BKT + j > q0 + i) s = -1e30f;
                Ps[i * STR + j] = s;
            }
        }
        __syncthreads();

        // ---- row softmax (one thread per query row) ------------------
        if (tid < BQ) {
            float* row = Ps + tid * STR;
            float mx = -1e30f;
#pragma unroll 8
            for (int j = 0; j < BKT; j++) mx = fmaxf(mx, row[j]);
            const float mo = mS[tid];
            const float mn = fmaxf(mo, mx);
            const float corr = __expf(mo - mn);
            float sum = 0.f;
#pragma unroll 8
            for (int j = 0; j < BKT; j++) {
                const float p = __expf(row[j] - mn);
                row[j] = p;
                sum += p;
            }
            lS[tid] = lS[tid] * corr + sum;
            mS[tid] = mn;
            cS[tid] = corr;
        }
        __syncthreads();

        // ---- rescale O, GEMM-B: O += P . V ---------------------------
        float cr[8];
#pragma unroll
        for (int ii = 0; ii < 8; ii++) cr[ii] = cS[ty * 8 + ii];
#pragma unroll
        for (int ii = 0; ii < 8; ii++)
#pragma unroll
            for (int c = 0; c < 4; c++) O[ii][c] *= cr[ii];

#pragma unroll 4
        for (int j = 0; j < BKT; j++) {
            const float4 vv = *(const float4*)&Vs[j * STR + tx * 4];
#pragma unroll
            for (int ii = 0; ii < 8; ii++) {
                const float p = Ps[(ty * 8 + ii) * STR + j];
                O[ii][0] = fmaf(p, vv.x, O[ii][0]);
                O[ii][1] = fmaf(p, vv.y, O[ii][1]);
                O[ii][2] = fmaf(p, vv.z, O[ii][2]);
                O[ii][3] = fmaf(p, vv.w, O[ii][3]);
            }
        }
    }

    // Epilogue: normalize and store (lS stable since last softmax sync)
#pragma unroll
    for (int ii = 0; ii < 8; ii++) {
        const int i = ty * 8 + ii;
        const float inv = 1.f / lS[i];
        *(float4*)&g_att[qgbase + (size_t)i * DM + tx * 4] =
            make_float4(O[ii][0] * inv, O[ii][1] * inv, O[ii][2] * inv, O[ii][3] * inv);
    }
}

// ---------------------------------------------------------------------------
extern "C" void kernel_launch(void* const* d_in, const int* in_sizes, int n_in,
                              void* d_out, int out_size)
{
    const float* x  = (const float*)d_in[0];
    const float* Wq = (const float*)d_in[1];
    const float* Wk = (const float*)d_in[2];
    const float* Wv = (const float*)d_in[3];
    const float* Wo = (const float*)d_in[4];
    float* out = (float*)d_out;

    static int smem_set = 0;
    if (!smem_set) {
        cudaFuncSetAttribute(attn_kernel,
                             cudaFuncAttributeMaxDynamicSharedMemorySize, ATT_SMEM);
        smem_set = 1;
    }

    dim3 gq(DM / 128, MR / 128, 3);
    qkv_kernel<<<gq, 256>>>(x, Wq, Wk, Wv);

    dim3 ga(TSEQ / BQ, NH, BB);
    attn_kernel<<<ga, 256, ATT_SMEM>>>();

    dim3 gp(DM / 128, MR / 128, 1);
    proj_kernel<<<gp, 256>>>(Wo, out);
}

// round 9
// speedup vs baseline: 2.1491x; 1.3699x over previous
#include <cuda_runtime.h>
#include <cuda_bf16.h>
#include <cstdint>

#define TSEQ 2048
#define BB 2
#define DM 1024
#define NH 16
#define HD 64
#define MR (BB*TSEQ)   // 4096 rows

// ---------------------------------------------------------------------------
// Scratch (allocation-free rule: __device__ globals)
// ---------------------------------------------------------------------------
__device__ float g_q[(size_t)MR * DM];
__device__ float g_k[(size_t)MR * DM];
__device__ float g_v[(size_t)MR * DM];
__device__ float g_att[(size_t)MR * DM];

__device__ __nv_bfloat16 g_xh[(size_t)MR * DM];
__device__ __nv_bfloat16 g_xl[(size_t)MR * DM];
__device__ __nv_bfloat16 g_ah[(size_t)MR * DM];
__device__ __nv_bfloat16 g_al[(size_t)MR * DM];
__device__ __nv_bfloat16 g_wh[4][(size_t)DM * DM];
__device__ __nv_bfloat16 g_wl[4][(size_t)DM * DM];

// ---------------------------------------------------------------------------
// Warp MMA helpers (base-ISA: ldmatrix + mma.sync, legal on sm_103 target)
// ---------------------------------------------------------------------------
__device__ __forceinline__ uint32_t smem_u32(const void* p) {
    uint32_t a;
    asm("{ .reg .u64 t; cvta.to.shared.u64 t, %1; cvt.u32.u64 %0, t; }" : "=r"(a) : "l"(p));
    return a;
}
__device__ __forceinline__ void ldsm4(uint32_t (&r)[4], uint32_t addr) {
    asm volatile("ldmatrix.sync.aligned.m8n8.x4.shared.b16 {%0,%1,%2,%3}, [%4];"
                 : "=r"(r[0]), "=r"(r[1]), "=r"(r[2]), "=r"(r[3]) : "r"(addr));
}
__device__ __forceinline__ void mma16816(float* c, const uint32_t* a, const uint32_t* b) {
    asm volatile("mma.sync.aligned.m16n8k16.row.col.f32.bf16.bf16.f32 "
                 "{%0,%1,%2,%3},{%4,%5,%6,%7},{%8,%9},{%0,%1,%2,%3};"
                 : "+f"(c[0]), "+f"(c[1]), "+f"(c[2]), "+f"(c[3])
                 : "r"(a[0]), "r"(a[1]), "r"(a[2]), "r"(a[3]), "r"(b[0]), "r"(b[1]));
}

// ---------------------------------------------------------------------------
// fp32 -> bf16 hi/lo split.  mode: 0=x, 1..4=W[mode-1], 5=g_att
// ---------------------------------------------------------------------------
__global__ __launch_bounds__(256) void split_kernel(const float* __restrict__ src,
                                                    int mode, int n4)
{
    const int i = blockIdx.x * 256 + threadIdx.x;
    if (i >= n4) return;
    __nv_bfloat16 *h, *l;
    const float* s = src;
    if (mode == 0)      { h = g_xh; l = g_xl; }
    else if (mode <= 4) { h = g_wh[mode - 1]; l = g_wl[mode - 1]; }
    else                { h = g_ah; l = g_al; s = g_att; }

    const float4 v = ((const float4*)s)[i];
    const __nv_bfloat16 h0 = __float2bfloat16(v.x);
    const __nv_bfloat16 h1 = __float2bfloat16(v.y);
    const __nv_bfloat16 h2 = __float2bfloat16(v.z);
    const __nv_bfloat16 h3 = __float2bfloat16(v.w);
    const __nv_bfloat16 l0 = __float2bfloat16(v.x - __bfloat162float(h0));
    const __nv_bfloat16 l1 = __float2bfloat16(v.y - __bfloat162float(h1));
    const __nv_bfloat16 l2 = __float2bfloat16(v.z - __bfloat162float(h2));
    const __nv_bfloat16 l3 = __float2bfloat16(v.w - __bfloat162float(h3));
    ((__nv_bfloat162*)h)[2 * i]     = __halves2bfloat162(h0, h1);
    ((__nv_bfloat162*)h)[2 * i + 1] = __halves2bfloat162(h2, h3);
    ((__nv_bfloat162*)l)[2 * i]     = __halves2bfloat162(l0, l1);
    ((__nv_bfloat162*)l)[2 * i + 1] = __halves2bfloat162(l2, l3);
}

// ---------------------------------------------------------------------------
// Tensor-core GEMM (HMMA): Y[m,n] = sum_k A[m,k]*B[n,k], fp32 via bf16 split.
// Y = Ah.Bh^T + Ah.Bl^T + Al.Bh^T  -> 96 virtual BK=32 chunks (3 passes x 32).
// Tile 128x128, 256 thr = 8 warps (2m x 4n), warp tile 64x32 = 4x4 m16n8k16.
// Smem double-buffered, row stride 40 bf16 (conflict-free ldmatrix).
// ---------------------------------------------------------------------------
#define ASTR 40

__global__ __launch_bounds__(256) void tgemm_kernel(int mode, float* __restrict__ outp)
{
    __shared__ __nv_bfloat16 sA[2][128 * ASTR];   // 20480 B
    __shared__ __nv_bfloat16 sB[2][128 * ASTR];   // 20480 B

    const int tid  = threadIdx.x;
    const int lane = tid & 31;
    const int wid  = tid >> 5;
    const int warp_m = wid & 1;     // 0..1
    const int warp_n = wid >> 1;    // 0..3

    const int z = (mode == 3) ? 3 : (int)blockIdx.z;
    const __nv_bfloat16* Ah = (mode == 3) ? g_ah : g_xh;
    const __nv_bfloat16* Al = (mode == 3) ? g_al : g_xl;
    const __nv_bfloat16* Bh = g_wh[z];
    const __nv_bfloat16* Bl = g_wl[z];
    float* Y = (mode == 3) ? outp : (z == 0 ? g_q : (z == 1 ? g_k : g_v));

    const int tm = blockIdx.y;   // 0..31
    const int tn = blockIdx.x;   // 0..7

    const uint32_t sA_u = smem_u32(sA);
    const uint32_t sB_u = smem_u32(sB);

    // per-thread load mapping: item -> (row, 8-elem chunk)
    const int r0 = tid >> 2, c0 = (tid & 3) << 3;             // item tid
    const int r1 = (tid + 256) >> 2, c1 = ((tid + 256) & 3) << 3;

    // ldmatrix fragment addresses (element offsets within a buffer)
    const int a_row = warp_m * 64 + (lane & 15);
    const int a_col = (lane >> 4) << 3;
    const int bgrp  = lane >> 3;
    const int b_row = warp_n * 32 + ((bgrp >= 2) ? 8 : 0) + (lane & 7);
    const int b_col = (bgrp & 1) << 3;

    float acc[4][4][4];
#pragma unroll
    for (int i = 0; i < 4; i++)
#pragma unroll
        for (int j = 0; j < 4; j++)
#pragma unroll
            for (int k = 0; k < 4; k++) acc[i][j][k] = 0.f;

    // chunk c: pass = c>>5, kc = c&31
    auto gsrc = [&](int c, const __nv_bfloat16*& Ag, const __nv_bfloat16*& Bg) {
        const int pass = c >> 5, kc = c & 31;
        const __nv_bfloat16* Ap = (pass == 2) ? Al : Ah;
        const __nv_bfloat16* Bp = (pass == 1) ? Bl : Bh;
        Ag = Ap + (size_t)(tm * 128) * DM + kc * 32;
        Bg = Bp + (size_t)(tn * 128) * DM + kc * 32;
    };

    // prologue: chunk 0 -> buf 0
    {
        const __nv_bfloat16 *Ag, *Bg;
        gsrc(0, Ag, Bg);
        *(uint4*)&sA[0][r0 * ASTR + c0] = *(const uint4*)(Ag + (size_t)r0 * DM + c0);
        *(uint4*)&sA[0][r1 * ASTR + c1] = *(const uint4*)(Ag + (size_t)r1 * DM + c1);
        *(uint4*)&sB[0][r0 * ASTR + c0] = *(const uint4*)(Bg + (size_t)r0 * DM + c0);
        *(uint4*)&sB[0][r1 * ASTR + c1] = *(const uint4*)(Bg + (size_t)r1 * DM + c1);
    }
    __syncthreads();

    int buf = 0;
    for (int c = 0; c < 96; c++) {
        uint4 na0, na1, nb0, nb1;
        if (c < 95) {
            const __nv_bfloat16 *Ag, *Bg;
            gsrc(c + 1, Ag, Bg);
            na0 = *(const uint4*)(Ag + (size_t)r0 * DM + c0);
            na1 = *(const uint4*)(Ag + (size_t)r1 * DM + c1);
            nb0 = *(const uint4*)(Bg + (size_t)r0 * DM + c0);
            nb1 = *(const uint4*)(Bg + (size_t)r1 * DM + c1);
        }

        const uint32_t abase = sA_u + (uint32_t)(buf * 128 * ASTR) * 2;
        const uint32_t bbase = sB_u + (uint32_t)(buf * 128 * ASTR) * 2;
#pragma unroll
        for (int ks = 0; ks < 2; ks++) {
            uint32_t af[4][4];
#pragma unroll
            for (int mt = 0; mt < 4; mt++)
                ldsm4(af[mt], abase + (uint32_t)((a_row + mt * 16) * ASTR + ks * 16 + a_col) * 2);
            uint32_t bfr[2][4];
#pragma unroll
            for (int np = 0; np < 2; np++)
                ldsm4(bfr[np], bbase + (uint32_t)((b_row + np * 16) * ASTR + ks * 16 + b_col) * 2);
#pragma unroll
            for (int mt = 0; mt < 4; mt++)
#pragma unroll
                for (int nt = 0; nt < 4; nt++)
                    mma16816(acc[mt][nt], af[mt], &bfr[nt >> 1][(nt & 1) * 2]);
        }

        if (c < 95) {
            const int nb = buf ^ 1;
            *(uint4*)&sA[nb][r0 * ASTR + c0] = na0;
            *(uint4*)&sA[nb][r1 * ASTR + c1] = na1;
            *(uint4*)&sB[nb][r0 * ASTR + c0] = nb0;
            *(uint4*)&sB[nb][r1 * ASTR + c1] = nb1;
        }
        __syncthreads();
        buf ^= 1;
    }

    // epilogue: D fragment (row = lane/4, col pair = 2*(lane%4))
    float* Yp = Y + (size_t)(tm * 128 + warp_m * 64) * DM + tn * 128 + warp_n * 32;
    const int dr = lane >> 2, dc = (lane & 3) << 1;
#pragma unroll
    for (int mt = 0; mt < 4; mt++)
#pragma unroll
        for (int nt = 0; nt < 4; nt++) {
            *(float2*)&Yp[(size_t)(mt * 16 + dr) * DM + nt * 8 + dc] =
                make_float2(acc[mt][nt][0], acc[mt][nt][1]);
            *(float2*)&Yp[(size_t)(mt * 16 + 8 + dr) * DM + nt * 8 + dc] =
                make_float2(acc[mt][nt][2], acc[mt][nt][3]);
        }
}

// ---------------------------------------------------------------------------
// Flash attention as two block-GEMMs per K-tile (unchanged; known-good).
// ---------------------------------------------------------------------------
#define BQ  128
#define BKT 64
#define STR 68
#define ATT_SMEM ((BQ*STR + BKT*STR + BKT*STR + BQ*STR + 3*BQ) * 4)

__global__ __launch_bounds__(256) void attn_kernel()
{
    extern __shared__ float sm[];
    float* Qs = sm;                    // [128][68]
    float* Ks = Qs + BQ * STR;         // [64][68]
    float* Vs = Ks + BKT * STR;        // [64][68]
    float* Ps = Vs + BKT * STR;        // [128][68]
    float* mS = Ps + BQ * STR;         // [128]
    float* lS = mS + BQ;               // [128]
    float* cS = lS + BQ;               // [128]

    const int tid = threadIdx.x;
    const int tx = tid & 15;
    const int ty = tid >> 4;
    const int xb = gridDim.x - 1 - blockIdx.x;   // heavy blocks first
    const int q0 = xb * BQ;
    const int h  = blockIdx.y;
    const int b  = blockIdx.z;

    const size_t qgbase = (size_t)(b * TSEQ + q0) * DM + h * HD;
    for (int idx = tid; idx < BQ * HD; idx += 256) {
        const int i = idx >> 6, d = idx & 63;
        Qs[i * STR + d] = g_q[qgbase + (size_t)i * DM + d];
    }
    if (tid < BQ) { mS[tid] = -1e30f; lS[tid] = 0.f; }

    float O[8][4];
#pragma unroll
    for (int i = 0; i < 8; i++)
#pragma unroll
        for (int c = 0; c < 4; c++) O[i][c] = 0.f;

    const int ntiles = 2 * (xb + 1);
    for (int t = 0; t < ntiles; t++) {
        __syncthreads();

        const size_t kg = (size_t)(b * TSEQ + t * BKT) * DM + h * HD;
        for (int idx = tid; idx < BKT * HD; idx += 256) {
            const int j = idx >> 6, d = idx & 63;
            Ks[j * STR + d] = g_k[kg + (size_t)j * DM + d];
            Vs[j * STR + d] = g_v[kg + (size_t)j * DM + d];
        }
        __syncthreads();

        float acc[8][4];
#pragma unroll
        for (int i = 0; i < 8; i++)
#pragma unroll
            for (int j = 0; j < 4; j++) acc[i][j] = 0.f;

#pragma unroll 2
        for (int d4 = 0; d4 < 16; d4++) {
#pragma unroll
            for (int hh = 0; hh < 2; hh++) {
                float4 qv[4];
#pragma unroll
                for (int r = 0; r < 4; r++)
                    qv[r] = *(const float4*)&Qs[(ty * 8 + hh * 4 + r) * STR + d4 * 4];
#pragma unroll
                for (int jj = 0; jj < 4; jj++) {
                    const float4 kv = *(const float4*)&Ks[(tx + 16 * jj) * STR + d4 * 4];
#pragma unroll
                    for (int r = 0; r < 4; r++) {
                        acc[hh * 4 + r][jj] = fmaf(qv[r].x, kv.x, acc[hh * 4 + r][jj]);
                        acc[hh * 4 + r][jj] = fmaf(qv[r].y, kv.y, acc[hh * 4 + r][jj]);
                        acc[hh * 4 + r][jj] = fmaf(qv[r].z, kv.z, acc[hh * 4 + r][jj]);
                        acc[hh * 4 + r][jj] = fmaf(qv[r].w, kv.w, acc[hh * 4 + r][jj]);
                    }
                }
            }
        }

#pragma unroll
        for (int ii = 0; ii < 8; ii++) {
            const int i = ty * 8 + ii;
#pragma unroll
            for (int jj = 0; jj < 4; jj++) {
                const int j = tx + 16 * jj;
                float s = acc[ii][jj] * 0.125f;
                if (t * BKT + j > q0 + i) s = -1e30f;
                Ps[i * STR + j] = s;
            }
        }
        __syncthreads();

        if (tid < BQ) {
            float* row = Ps + tid * STR;
            float mx = -1e30f;
#pragma unroll 8
            for (int j = 0; j < BKT; j++) mx = fmaxf(mx, row[j]);
            const float mo = mS[tid];
            const float mn = fmaxf(mo, mx);
            const float corr = __expf(mo - mn);
            float sum = 0.f;
#pragma unroll 8
            for (int j = 0; j < BKT; j++) {
                const float p = __expf(row[j] - mn);
                row[j] = p;
                sum += p;
            }
            lS[tid] = lS[tid] * corr + sum;
            mS[tid] = mn;
            cS[tid] = corr;
        }
        __syncthreads();

        float cr[8];
#pragma unroll
        for (int ii = 0; ii < 8; ii++) cr[ii] = cS[ty * 8 + ii];
#pragma unroll
        for (int ii = 0; ii < 8; ii++)
#pragma unroll
            for (int c = 0; c < 4; c++) O[ii][c] *= cr[ii];

#pragma unroll 4
        for (int j = 0; j < BKT; j++) {
            const float4 vv = *(const float4*)&Vs[j * STR + tx * 4];
#pragma unroll
            for (int ii = 0; ii < 8; ii++) {
                const float p = Ps[(ty * 8 + ii) * STR + j];
                O[ii][0] = fmaf(p, vv.x, O[ii][0]);
                O[ii][1] = fmaf(p, vv.y, O[ii][1]);
                O[ii][2] = fmaf(p, vv.z, O[ii][2]);
                O[ii][3] = fmaf(p, vv.w, O[ii][3]);
            }
        }
    }

#pragma unroll
    for (int ii = 0; ii < 8; ii++) {
        const int i = ty * 8 + ii;
        const float inv = 1.f / lS[i];
        *(float4*)&g_att[qgbase + (size_t)i * DM + tx * 4] =
            make_float4(O[ii][0] * inv, O[ii][1] * inv, O[ii][2] * inv, O[ii][3] * inv);
    }
}

// ---------------------------------------------------------------------------
extern "C" void kernel_launch(void* const* d_in, const int* in_sizes, int n_in,
                              void* d_out, int out_size)
{
    const float* x  = (const float*)d_in[0];
    const float* Wq = (const float*)d_in[1];
    const float* Wk = (const float*)d_in[2];
    const float* Wv = (const float*)d_in[3];
    const float* Wo = (const float*)d_in[4];
    float* out = (float*)d_out;

    static int init_done = 0;
    if (!init_done) {
        cudaFuncSetAttribute(attn_kernel,
                             cudaFuncAttributeMaxDynamicSharedMemorySize, ATT_SMEM);
        init_done = 1;
    }

    // bf16 hi/lo splits
    split_kernel<<<4096, 256>>>(x,  0, (MR * DM) / 4);
    split_kernel<<<1024, 256>>>(Wq, 1, (DM * DM) / 4);
    split_kernel<<<1024, 256>>>(Wk, 2, (DM * DM) / 4);
    split_kernel<<<1024, 256>>>(Wv, 3, (DM * DM) / 4);
    split_kernel<<<1024, 256>>>(Wo, 4, (DM * DM) / 4);

    dim3 gq(DM / 128, MR / 128, 3);
    tgemm_kernel<<<gq, 256>>>(0, nullptr);

    dim3 ga(TSEQ / BQ, NH, BB);
    attn_kernel<<<ga, 256, ATT_SMEM>>>();

    split_kernel<<<4096, 256>>>(nullptr, 5, (MR * DM) / 4);

    dim3 gp(DM / 128, MR / 128, 1);
    tgemm_kernel<<<gp, 256>>>(3, out);
}

// round 12
// speedup vs baseline: 3.5693x; 1.6609x over previous
#include <cuda_runtime.h>
#include <cuda_bf16.h>
#include <cstdint>

#define TSEQ 2048
#define BB 2
#define DM 1024
#define NH 16
#define HD 64
#define MR (BB*TSEQ)   // 4096 rows

// ---------------------------------------------------------------------------
// Scratch (allocation-free rule: __device__ globals) — all bf16 hi/lo pairs
// ---------------------------------------------------------------------------
__device__ __nv_bfloat16 g_xh[(size_t)MR * DM];
__device__ __nv_bfloat16 g_xl[(size_t)MR * DM];
__device__ __nv_bfloat16 g_qh[(size_t)MR * DM];
__device__ __nv_bfloat16 g_ql[(size_t)MR * DM];
__device__ __nv_bfloat16 g_kh[(size_t)MR * DM];
__device__ __nv_bfloat16 g_kl[(size_t)MR * DM];
__device__ __nv_bfloat16 g_vh[(size_t)MR * DM];
__device__ __nv_bfloat16 g_vl[(size_t)MR * DM];
__device__ __nv_bfloat16 g_ah[(size_t)MR * DM];
__device__ __nv_bfloat16 g_al[(size_t)MR * DM];
__device__ __nv_bfloat16 g_wh[4][(size_t)DM * DM];
__device__ __nv_bfloat16 g_wl[4][(size_t)DM * DM];

// ---------------------------------------------------------------------------
// Warp MMA helpers (base-ISA: ldmatrix + mma.sync, legal on sm_103 target)
// ---------------------------------------------------------------------------
__device__ __forceinline__ uint32_t smem_u32(const void* p) {
    uint32_t a;
    asm("{ .reg .u64 t; cvta.to.shared.u64 t, %1; cvt.u32.u64 %0, t; }" : "=r"(a) : "l"(p));
    return a;
}
__device__ __forceinline__ void ldsm4(uint32_t (&r)[4], uint32_t addr) {
    asm volatile("ldmatrix.sync.aligned.m8n8.x4.shared.b16 {%0,%1,%2,%3}, [%4];"
                 : "=r"(r[0]), "=r"(r[1]), "=r"(r[2]), "=r"(r[3]) : "r"(addr));
}
__device__ __forceinline__ void ldsm4t(uint32_t (&r)[4], uint32_t addr) {
    asm volatile("ldmatrix.sync.aligned.m8n8.x4.trans.shared.b16 {%0,%1,%2,%3}, [%4];"
                 : "=r"(r[0]), "=r"(r[1]), "=r"(r[2]), "=r"(r[3]) : "r"(addr));
}
__device__ __forceinline__ void mma16816(float* c, const uint32_t* a, const uint32_t* b) {
    asm volatile("mma.sync.aligned.m16n8k16.row.col.f32.bf16.bf16.f32 "
                 "{%0,%1,%2,%3},{%4,%5,%6,%7},{%8,%9},{%0,%1,%2,%3};"
                 : "+f"(c[0]), "+f"(c[1]), "+f"(c[2]), "+f"(c[3])
                 : "r"(a[0]), "r"(a[1]), "r"(a[2]), "r"(a[3]), "r"(b[0]), "r"(b[1]));
}
__device__ __forceinline__ uint32_t packbf(float a, float b) {
    __nv_bfloat162 t = __floats2bfloat162_rn(a, b);   // x = a (low), y = b
    return *(uint32_t*)&t;
}

// ---------------------------------------------------------------------------
// fp32 -> bf16 hi/lo split.  mode: 0=x, 1..4=W[mode-1]
// ---------------------------------------------------------------------------
__global__ __launch_bounds__(256) void split_kernel(const float* __restrict__ src,
                                                    int mode, int n4)
{
    const int i = blockIdx.x * 256 + threadIdx.x;
    if (i >= n4) return;
    __nv_bfloat16 *h, *l;
    if (mode == 0) { h = g_xh; l = g_xl; }
    else           { h = g_wh[mode - 1]; l = g_wl[mode - 1]; }

    const float4 v = ((const float4*)src)[i];
    const __nv_bfloat16 h0 = __float2bfloat16(v.x);
    const __nv_bfloat16 h1 = __float2bfloat16(v.y);
    const __nv_bfloat16 h2 = __float2bfloat16(v.z);
    const __nv_bfloat16 h3 = __float2bfloat16(v.w);
    const __nv_bfloat16 l0 = __float2bfloat16(v.x - __bfloat162float(h0));
    const __nv_bfloat16 l1 = __float2bfloat16(v.y - __bfloat162float(h1));
    const __nv_bfloat16 l2 = __float2bfloat16(v.z - __bfloat162float(h2));
    const __nv_bfloat16 l3 = __float2bfloat16(v.w - __bfloat162float(h3));
    ((__nv_bfloat162*)h)[2 * i]     = __halves2bfloat162(h0, h1);
    ((__nv_bfloat162*)h)[2 * i + 1] = __halves2bfloat162(h2, h3);
    ((__nv_bfloat162*)l)[2 * i]     = __halves2bfloat162(l0, l1);
    ((__nv_bfloat162*)l)[2 * i + 1] = __halves2bfloat162(l2, l3);
}

// ---------------------------------------------------------------------------
// Tensor-core GEMM (HMMA): Y[m,n] = sum_k A[m,k]*B[n,k], fp32 via bf16 split.
// mode 0: qkv (z = blockIdx.z), epilogue writes hi/lo bf16 to g_{q,k,v}{h,l}.
// mode 3: proj, A = g_ah/g_al, epilogue writes fp32 to outp.
// ---------------------------------------------------------------------------
#define ASTR 40

__global__ __launch_bounds__(256) void tgemm_kernel(int mode, float* __restrict__ outp)
{
    __shared__ __nv_bfloat16 sA[2][128 * ASTR];
    __shared__ __nv_bfloat16 sB[2][128 * ASTR];

    const int tid  = threadIdx.x;
    const int lane = tid & 31;
    const int wid  = tid >> 5;
    const int warp_m = wid & 1;
    const int warp_n = wid >> 1;

    const int z = (mode == 3) ? 3 : (int)blockIdx.z;
    const __nv_bfloat16* Ah = (mode == 3) ? g_ah : g_xh;
    const __nv_bfloat16* Al = (mode == 3) ? g_al : g_xl;
    const __nv_bfloat16* Bh = g_wh[z];
    const __nv_bfloat16* Bl = g_wl[z];

    const int tm = blockIdx.y;
    const int tn = blockIdx.x;

    const uint32_t sA_u = smem_u32(sA);
    const uint32_t sB_u = smem_u32(sB);

    const int r0 = tid >> 2, c0 = (tid & 3) << 3;
    const int r1 = (tid + 256) >> 2, c1 = ((tid + 256) & 3) << 3;

    const int a_row = warp_m * 64 + (lane & 15);
    const int a_col = (lane >> 4) << 3;
    const int bgrp  = lane >> 3;
    const int b_row = warp_n * 32 + ((bgrp >= 2) ? 8 : 0) + (lane & 7);
    const int b_col = (bgrp & 1) << 3;

    float acc[4][4][4];
#pragma unroll
    for (int i = 0; i < 4; i++)
#pragma unroll
        for (int j = 0; j < 4; j++)
#pragma unroll
            for (int k = 0; k < 4; k++) acc[i][j][k] = 0.f;

    auto gsrc = [&](int c, const __nv_bfloat16*& Ag, const __nv_bfloat16*& Bg) {
        const int pass = c >> 5, kc = c & 31;
        const __nv_bfloat16* Ap = (pass == 2) ? Al : Ah;
        const __nv_bfloat16* Bp = (pass == 1) ? Bl : Bh;
        Ag = Ap + (size_t)(tm * 128) * DM + kc * 32;
        Bg = Bp + (size_t)(tn * 128) * DM + kc * 32;
    };

    {
        const __nv_bfloat16 *Ag, *Bg;
        gsrc(0, Ag, Bg);
        *(uint4*)&sA[0][r0 * ASTR + c0] = *(const uint4*)(Ag + (size_t)r0 * DM + c0);
        *(uint4*)&sA[0][r1 * ASTR + c1] = *(const uint4*)(Ag + (size_t)r1 * DM + c1);
        *(uint4*)&sB[0][r0 * ASTR + c0] = *(const uint4*)(Bg + (size_t)r0 * DM + c0);
        *(uint4*)&sB[0][r1 * ASTR + c1] = *(const uint4*)(Bg + (size_t)r1 * DM + c1);
    }
    __syncthreads();

    int buf = 0;
    for (int c = 0; c < 96; c++) {
        uint4 na0, na1, nb0, nb1;
        if (c < 95) {
            const __nv_bfloat16 *Ag, *Bg;
            gsrc(c + 1, Ag, Bg);
            na0 = *(const uint4*)(Ag + (size_t)r0 * DM + c0);
            na1 = *(const uint4*)(Ag + (size_t)r1 * DM + c1);
            nb0 = *(const uint4*)(Bg + (size_t)r0 * DM + c0);
            nb1 = *(const uint4*)(Bg + (size_t)r1 * DM + c1);
        }

        const uint32_t abase = sA_u + (uint32_t)(buf * 128 * ASTR) * 2;
        const uint32_t bbase = sB_u + (uint32_t)(buf * 128 * ASTR) * 2;
#pragma unroll
        for (int ks = 0; ks < 2; ks++) {
            uint32_t af[4][4];
#pragma unroll
            for (int mt = 0; mt < 4; mt++)
                ldsm4(af[mt], abase + (uint32_t)((a_row + mt * 16) * ASTR + ks * 16 + a_col) * 2);
            uint32_t bfr[2][4];
#pragma unroll
            for (int np = 0; np < 2; np++)
                ldsm4(bfr[np], bbase + (uint32_t)((b_row + np * 16) * ASTR + ks * 16 + b_col) * 2);
#pragma unroll
            for (int mt = 0; mt < 4; mt++)
#pragma unroll
                for (int nt = 0; nt < 4; nt++)
                    mma16816(acc[mt][nt], af[mt], &bfr[nt >> 1][(nt & 1) * 2]);
        }

        if (c < 95) {
            const int nb = buf ^ 1;
            *(uint4*)&sA[nb][r0 * ASTR + c0] = na0;
            *(uint4*)&sA[nb][r1 * ASTR + c1] = na1;
            *(uint4*)&sB[nb][r0 * ASTR + c0] = nb0;
            *(uint4*)&sB[nb][r1 * ASTR + c1] = nb1;
        }
        __syncthreads();
        buf ^= 1;
    }

    const int dr = lane >> 2, dc = (lane & 3) << 1;
    const int mbase = tm * 128 + warp_m * 64;
    const int nbase = tn * 128 + warp_n * 32;

    if (mode == 3) {
        float* Yp = outp + (size_t)mbase * DM + nbase;
#pragma unroll
        for (int mt = 0; mt < 4; mt++)
#pragma unroll
            for (int nt = 0; nt < 4; nt++) {
                *(float2*)&Yp[(size_t)(mt * 16 + dr) * DM + nt * 8 + dc] =
                    make_float2(acc[mt][nt][0], acc[mt][nt][1]);
                *(float2*)&Yp[(size_t)(mt * 16 + 8 + dr) * DM + nt * 8 + dc] =
                    make_float2(acc[mt][nt][2], acc[mt][nt][3]);
            }
    } else {
        __nv_bfloat16* Yh = (z == 0) ? g_qh : (z == 1 ? g_kh : g_vh);
        __nv_bfloat16* Yl = (z == 0) ? g_ql : (z == 1 ? g_kl : g_vl);
#pragma unroll
        for (int mt = 0; mt < 4; mt++)
#pragma unroll
            for (int nt = 0; nt < 4; nt++) {
#pragma unroll
                for (int half = 0; half < 2; half++) {
                    const float va = acc[mt][nt][half * 2];
                    const float vb = acc[mt][nt][half * 2 + 1];
                    const __nv_bfloat16 ha = __float2bfloat16(va);
                    const __nv_bfloat16 hb = __float2bfloat16(vb);
                    const float la = va - __bfloat162float(ha);
                    const float lb = vb - __bfloat162float(hb);
                    const size_t off = (size_t)(mbase + mt * 16 + half * 8 + dr) * DM
                                       + nbase + nt * 8 + dc;
                    __nv_bfloat162 hp = __halves2bfloat162(ha, hb);
                    *(uint32_t*)&Yh[off] = *(uint32_t*)&hp;
                    *(uint32_t*)&Yl[off] = packbf(la, lb);
                }
            }
    }
}

// ---------------------------------------------------------------------------
// Flash attention (FA2-style, HMMA). Grid (16, NH, BB), 256 threads = 8 warps.
// Block: 128 q-rows; warp: 16 q-rows. K-tiles of 64 keys, D = 64.
// QK: 3-pass bf16 split; PV: 3-pass bf16 split; softmax on fragments.
// ---------------------------------------------------------------------------
#define KSTR 72   // smem row stride (bf16): 144B, 16B-aligned, conflict-free

__global__ __launch_bounds__(256) void attn_kernel()
{
    __shared__ __nv_bfloat16 sKh[64 * KSTR], sKl[64 * KSTR];
    __shared__ __nv_bfloat16 sVh[64 * KSTR], sVl[64 * KSTR];

    const int tid  = threadIdx.x;
    const int lane = tid & 31;
    const int w    = tid >> 5;
    const int xb   = gridDim.x - 1 - blockIdx.x;   // heavy blocks first
    const int q0   = xb * 128;
    const int h    = blockIdx.y;
    const int b    = blockIdx.z;

    const int r0g  = q0 + w * 16 + (lane >> 2);
    const int r1g  = r0g + 8;
    const int qcol = (lane & 3) << 1;

    const uint32_t sKh_u = smem_u32(sKh), sKl_u = smem_u32(sKl);
    const uint32_t sVh_u = smem_u32(sVh), sVl_u = smem_u32(sVl);

    // K-fragment lane pattern (non-trans ldmatrix; matches validated GEMM)
    const int kb_row = ((lane >> 4) & 1) * 8 + (lane & 7);
    const int kb_col = ((lane >> 3) & 1) * 8;
    // V-fragment lane pattern (trans ldmatrix)
    const int vt_k = ((lane >> 3) & 1) * 8 + (lane & 7);
    const int vt_n = (lane >> 4) * 8;

    // Q fragments (hi/lo), loaded straight from gmem into mma A layout
    uint32_t qh[4][4], ql[4][4];
    {
        const size_t base0 = (size_t)(b * TSEQ + r0g) * DM + h * HD;
        const size_t base1 = (size_t)(b * TSEQ + r1g) * DM + h * HD;
#pragma unroll
        for (int ks = 0; ks < 4; ks++) {
            qh[ks][0] = *(const uint32_t*)&g_qh[base0 + ks * 16 + qcol];
            qh[ks][1] = *(const uint32_t*)&g_qh[base1 + ks * 16 + qcol];
            qh[ks][2] = *(const uint32_t*)&g_qh[base0 + ks * 16 + 8 + qcol];
            qh[ks][3] = *(const uint32_t*)&g_qh[base1 + ks * 16 + 8 + qcol];
            ql[ks][0] = *(const uint32_t*)&g_ql[base0 + ks * 16 + qcol];
            ql[ks][1] = *(const uint32_t*)&g_ql[base1 + ks * 16 + qcol];
            ql[ks][2] = *(const uint32_t*)&g_ql[base0 + ks * 16 + 8 + qcol];
            ql[ks][3] = *(const uint32_t*)&g_ql[base1 + ks * 16 + 8 + qcol];
        }
    }

    float O[8][4];
#pragma unroll
    for (int i = 0; i < 8; i++)
#pragma unroll
        for (int j = 0; j < 4; j++) O[i][j] = 0.f;
    float m0 = -1e30f, m1 = -1e30f, l0 = 0.f, l1 = 0.f;

    const int ntiles = 2 * xb + 2;
    for (int t = 0; t < ntiles; t++) {
        __syncthreads();
        // Stage K/V hi/lo tiles
#pragma unroll
        for (int i = 0; i < 2; i++) {
            const int li = tid + i * 256;
            const int row = li >> 3, ch = (li & 7) << 3;
            const size_t g = (size_t)(b * TSEQ + t * 64 + row) * DM + h * HD + ch;
            const int so = row * KSTR + ch;
            *(uint4*)&sKh[so] = *(const uint4*)&g_kh[g];
            *(uint4*)&sKl[so] = *(const uint4*)&g_kl[g];
            *(uint4*)&sVh[so] = *(const uint4*)&g_vh[g];
            *(uint4*)&sVl[so] = *(const uint4*)&g_vl[g];
        }
        __syncthreads();

        // ---- S = Q.K^T (3-pass split) --------------------------------
        float s[8][4];
#pragma unroll
        for (int i = 0; i < 8; i++)
#pragma unroll
            for (int j = 0; j < 4; j++) s[i][j] = 0.f;

#pragma unroll
        for (int ks = 0; ks < 4; ks++) {
#pragma unroll
            for (int np = 0; np < 4; np++) {
                uint32_t kh4[4], kl4[4];
                const uint32_t off =
                    (uint32_t)((np * 16 + kb_row) * KSTR + ks * 16 + kb_col) * 2;
                ldsm4(kh4, sKh_u + off);
                ldsm4(kl4, sKl_u + off);
                mma16816(s[np * 2],     qh[ks], &kh4[0]);
                mma16816(s[np * 2 + 1], qh[ks], &kh4[2]);
                mma16816(s[np * 2],     ql[ks], &kh4[0]);
                mma16816(s[np * 2 + 1], ql[ks], &kh4[2]);
                mma16816(s[np * 2],     qh[ks], &kl4[0]);
                mma16816(s[np * 2 + 1], qh[ks], &kl4[2]);
            }
        }

        // ---- scale + causal mask -------------------------------------
        const bool masked = (t >= 2 * xb);
#pragma unroll
        for (int nt = 0; nt < 8; nt++)
#pragma unroll
            for (int e = 0; e < 4; e++) {
                float v = s[nt][e] * 0.125f;
                if (masked) {
                    const int col = t * 64 + nt * 8 + qcol + (e & 1);
                    const int row = (e < 2) ? r0g : r1g;
                    if (col > row) v = -1e30f;
                }
                s[nt][e] = v;
            }

        // ---- online softmax on fragments -----------------------------
        float mx0 = -1e30f, mx1 = -1e30f;
#pragma unroll
        for (int nt = 0; nt < 8; nt++) {
            mx0 = fmaxf(mx0, fmaxf(s[nt][0], s[nt][1]));
            mx1 = fmaxf(mx1, fmaxf(s[nt][2], s[nt][3]));
        }
        mx0 = fmaxf(mx0, __shfl_xor_sync(0xffffffffu, mx0, 1));
        mx0 = fmaxf(mx0, __shfl_xor_sync(0xffffffffu, mx0, 2));
        mx1 = fmaxf(mx1, __shfl_xor_sync(0xffffffffu, mx1, 1));
        mx1 = fmaxf(mx1, __shfl_xor_sync(0xffffffffu, mx1, 2));

        const float mn0 = fmaxf(m0, mx0);
        const float mn1 = fmaxf(m1, mx1);
        const float corr0 = __expf(m0 - mn0);
        const float corr1 = __expf(m1 - mn1);
        m0 = mn0; m1 = mn1;

        uint32_t ph[4][4], pl[4][4];
        float sum0 = 0.f, sum1 = 0.f;
#pragma unroll
        for (int nt = 0; nt < 8; nt++) {
            const int ks = nt >> 1, ro = (nt & 1) * 2;
            const float p0 = __expf(s[nt][0] - mn0);
            const float p1 = __expf(s[nt][1] - mn0);
            const float p2 = __expf(s[nt][2] - mn1);
            const float p3 = __expf(s[nt][3] - mn1);
            sum0 += p0 + p1; sum1 += p2 + p3;
            const __nv_bfloat16 h0 = __float2bfloat16(p0);
            const __nv_bfloat16 h1 = __float2bfloat16(p1);
            const __nv_bfloat16 h2 = __float2bfloat16(p2);
            const __nv_bfloat16 h3 = __float2bfloat16(p3);
            __nv_bfloat162 t01 = __halves2bfloat162(h0, h1);
            __nv_bfloat162 t23 = __halves2bfloat162(h2, h3);
            ph[ks][ro]     = *(uint32_t*)&t01;
            ph[ks][ro + 1] = *(uint32_t*)&t23;
            pl[ks][ro]     = packbf(p0 - __bfloat162float(h0), p1 - __bfloat162float(h1));
            pl[ks][ro + 1] = packbf(p2 - __bfloat162float(h2), p3 - __bfloat162float(h3));
        }
        sum0 += __shfl_xor_sync(0xffffffffu, sum0, 1);
        sum0 += __shfl_xor_sync(0xffffffffu, sum0, 2);
        sum1 += __shfl_xor_sync(0xffffffffu, sum1, 1);
        sum1 += __shfl_xor_sync(0xffffffffu, sum1, 2);
        l0 = l0 * corr0 + sum0;
        l1 = l1 * corr1 + sum1;

#pragma unroll
        for (int nt = 0; nt < 8; nt++) {
            O[nt][0] *= corr0; O[nt][1] *= corr0;
            O[nt][2] *= corr1; O[nt][3] *= corr1;
        }

        // ---- O += P.V (3-pass split) ---------------------------------
#pragma unroll
        for (int ks = 0; ks < 4; ks++) {
#pragma unroll
            for (int np = 0; np < 4; np++) {
                uint32_t vh4[4], vl4[4];
                const uint32_t off =
                    (uint32_t)((ks * 16 + vt_k) * KSTR + np * 16 + vt_n) * 2;
                ldsm4t(vh4, sVh_u + off);
                ldsm4t(vl4, sVl_u + off);
                mma16816(O[np * 2],     ph[ks], &vh4[0]);
                mma16816(O[np * 2 + 1], ph[ks], &vh4[2]);
                mma16816(O[np * 2],     pl[ks], &vh4[0]);
                mma16816(O[np * 2 + 1], pl[ks], &vh4[2]);
                mma16816(O[np * 2],     ph[ks], &vl4[0]);
                mma16816(O[np * 2 + 1], ph[ks], &vl4[2]);
            }
        }
    }

    // ---- epilogue: normalize, split hi/lo, store --------------------
    const float inv0 = 1.f / l0;
    const float inv1 = 1.f / l1;
    const size_t ob0 = (size_t)(b * TSEQ + r0g) * DM + h * HD;
    const size_t ob1 = (size_t)(b * TSEQ + r1g) * DM + h * HD;
#pragma unroll
    for (int nt = 0; nt < 8; nt++) {
        const float v0 = O[nt][0] * inv0, v1 = O[nt][1] * inv0;
        const float v2 = O[nt][2] * inv1, v3 = O[nt][3] * inv1;
        const __nv_bfloat16 h0 = __float2bfloat16(v0);
        const __nv_bfloat16 h1 = __float2bfloat16(v1);
        const __nv_bfloat16 h2 = __float2bfloat16(v2);
        const __nv_bfloat16 h3 = __float2bfloat16(v3);
        __nv_bfloat162 t01 = __halves2bfloat162(h0, h1);
        __nv_bfloat162 t23 = __halves2bfloat162(h2, h3);
        *(uint32_t*)&g_ah[ob0 + nt * 8 + qcol] = *(uint32_t*)&t01;
        *(uint32_t*)&g_ah[ob1 + nt * 8 + qcol] = *(uint32_t*)&t23;
        *(uint32_t*)&g_al[ob0 + nt * 8 + qcol] =
            packbf(v0 - __bfloat162float(h0), v1 - __bfloat162float(h1));
        *(uint32_t*)&g_al[ob1 + nt * 8 + qcol] =
            packbf(v2 - __bfloat162float(h2), v3 - __bfloat162float(h3));
    }
}

// ---------------------------------------------------------------------------
extern "C" void kernel_launch(void* const* d_in, const int* in_sizes, int n_in,
                              void* d_out, int out_size)
{
    const float* x  = (const float*)d_in[0];
    const float* Wq = (const float*)d_in[1];
    const float* Wk = (const float*)d_in[2];
    const float* Wv = (const float*)d_in[3];
    const float* Wo = (const float*)d_in[4];
    float* out = (float*)d_out;

    // bf16 hi/lo splits for the GEMM inputs
    split_kernel<<<4096, 256>>>(x,  0, (MR * DM) / 4);
    split_kernel<<<1024, 256>>>(Wq, 1, (DM * DM) / 4);
    split_kernel<<<1024, 256>>>(Wk, 2, (DM * DM) / 4);
    split_kernel<<<1024, 256>>>(Wv, 3, (DM * DM) / 4);
    split_kernel<<<1024, 256>>>(Wo, 4, (DM * DM) / 4);

    dim3 gq(DM / 128, MR / 128, 3);
    tgemm_kernel<<<gq, 256>>>(0, nullptr);

    dim3 ga(TSEQ / 128, NH, BB);
    attn_kernel<<<ga, 256>>>();

    dim3 gp(DM / 128, MR / 128, 1);
    tgemm_kernel<<<gp, 256>>>(3, out);
}

// round 14
// speedup vs baseline: 4.1279x; 1.1565x over previous
#include <cuda_runtime.h>
#include <cuda_bf16.h>
#include <cstdint>

#define TSEQ 2048
#define BB 2
#define DM 1024
#define NH 16
#define HD 64
#define MR (BB*TSEQ)   // 4096 rows

// ---------------------------------------------------------------------------
// Scratch (allocation-free rule: __device__ globals) — all bf16 hi/lo pairs
// ---------------------------------------------------------------------------
__device__ __nv_bfloat16 g_xh[(size_t)MR * DM];
__device__ __nv_bfloat16 g_xl[(size_t)MR * DM];
__device__ __nv_bfloat16 g_qh[(size_t)MR * DM];
__device__ __nv_bfloat16 g_ql[(size_t)MR * DM];
__device__ __nv_bfloat16 g_kh[(size_t)MR * DM];
__device__ __nv_bfloat16 g_kl[(size_t)MR * DM];
__device__ __nv_bfloat16 g_vh[(size_t)MR * DM];
__device__ __nv_bfloat16 g_vl[(size_t)MR * DM];
__device__ __nv_bfloat16 g_ah[(size_t)MR * DM];
__device__ __nv_bfloat16 g_al[(size_t)MR * DM];
__device__ __nv_bfloat16 g_wh[4][(size_t)DM * DM];
__device__ __nv_bfloat16 g_wl[4][(size_t)DM * DM];

// ---------------------------------------------------------------------------
// Warp MMA helpers (base-ISA: ldmatrix + mma.sync + cp.async)
// ---------------------------------------------------------------------------
__device__ __forceinline__ uint32_t smem_u32(const void* p) {
    uint32_t a;
    asm("{ .reg .u64 t; cvta.to.shared.u64 t, %1; cvt.u32.u64 %0, t; }" : "=r"(a) : "l"(p));
    return a;
}
__device__ __forceinline__ void ldsm4(uint32_t (&r)[4], uint32_t addr) {
    asm volatile("ldmatrix.sync.aligned.m8n8.x4.shared.b16 {%0,%1,%2,%3}, [%4];"
                 : "=r"(r[0]), "=r"(r[1]), "=r"(r[2]), "=r"(r[3]) : "r"(addr));
}
__device__ __forceinline__ void ldsm4t(uint32_t (&r)[4], uint32_t addr) {
    asm volatile("ldmatrix.sync.aligned.m8n8.x4.trans.shared.b16 {%0,%1,%2,%3}, [%4];"
                 : "=r"(r[0]), "=r"(r[1]), "=r"(r[2]), "=r"(r[3]) : "r"(addr));
}
__device__ __forceinline__ void mma16816(float* c, const uint32_t* a, const uint32_t* b) {
    asm volatile("mma.sync.aligned.m16n8k16.row.col.f32.bf16.bf16.f32 "
                 "{%0,%1,%2,%3},{%4,%5,%6,%7},{%8,%9},{%0,%1,%2,%3};"
                 : "+f"(c[0]), "+f"(c[1]), "+f"(c[2]), "+f"(c[3])
                 : "r"(a[0]), "r"(a[1]), "r"(a[2]), "r"(a[3]), "r"(b[0]), "r"(b[1]));
}
__device__ __forceinline__ uint32_t packbf(float a, float b) {
    __nv_bfloat162 t = __floats2bfloat162_rn(a, b);
    return *(uint32_t*)&t;
}
__device__ __forceinline__ void cpasync16(uint32_t saddr, const void* g) {
    asm volatile("cp.async.cg.shared.global [%0], [%1], 16;" :: "r"(saddr), "l"(g) : "memory");
}

// ---------------------------------------------------------------------------
// Fused fp32 -> bf16 hi/lo split for x and all four weights in ONE launch.
// ---------------------------------------------------------------------------
#define XN4 ((MR * DM) / 4)    // 1,048,576
#define WN4 ((DM * DM) / 4)    // 262,144 = 2^18

__global__ __launch_bounds__(256) void split_all(const float* __restrict__ x,
                                                 const float* __restrict__ Wq,
                                                 const float* __restrict__ Wk,
                                                 const float* __restrict__ Wv,
                                                 const float* __restrict__ Wo)
{
    const int i = blockIdx.x * 256 + threadIdx.x;
    const float* s;
    __nv_bfloat16 *h, *l;
    int j;
    if (i < XN4) { s = x; h = g_xh; l = g_xl; j = i; }
    else {
        const int k = i - XN4;
        const int w = k >> 18;
        j = k & (WN4 - 1);
        s = (w == 0) ? Wq : (w == 1) ? Wk : (w == 2) ? Wv : Wo;
        h = g_wh[w]; l = g_wl[w];
    }
    const float4 v = ((const float4*)s)[j];
    const __nv_bfloat16 h0 = __float2bfloat16(v.x);
    const __nv_bfloat16 h1 = __float2bfloat16(v.y);
    const __nv_bfloat16 h2 = __float2bfloat16(v.z);
    const __nv_bfloat16 h3 = __float2bfloat16(v.w);
    ((__nv_bfloat162*)h)[2 * j]     = __halves2bfloat162(h0, h1);
    ((__nv_bfloat162*)h)[2 * j + 1] = __halves2bfloat162(h2, h3);
    *(uint32_t*)&((__nv_bfloat162*)l)[2 * j]     = packbf(v.x - __bfloat162float(h0), v.y - __bfloat162float(h1));
    *(uint32_t*)&((__nv_bfloat162*)l)[2 * j + 1] = packbf(v.z - __bfloat162float(h2), v.w - __bfloat162float(h3));
}

// ---------------------------------------------------------------------------
// Tensor-core GEMM (HMMA): Y[m,n] = sum_k A[m,k]*B[n,k], fp32 via bf16 split.
// Stage Ah/Al/Bh/Bl together per BK=32 chunk (32 chunks), 3 MMA pass-groups
// per chunk. cp.async 2-stage pipeline, 80 KB dynamic smem.
// mode 0: qkv (z = blockIdx.z), epilogue -> hi/lo bf16 g_{q,k,v}{h,l}.
// mode 3: proj, A = g_ah/g_al, epilogue -> fp32 outp.
// ---------------------------------------------------------------------------
#define ASTR 40
#define TILE_ELEMS (128 * ASTR)           // 5120 bf16
#define GSMEM_BYTES (8 * TILE_ELEMS * 2)  // 81920

__global__ __launch_bounds__(256) void tgemm_kernel(int mode, float* __restrict__ outp)
{
    extern __shared__ __nv_bfloat16 dsm[];
    const uint32_t dsm_u = smem_u32(dsm);

    const int tid  = threadIdx.x;
    const int lane = tid & 31;
    const int wid  = tid >> 5;
    const int warp_m = wid & 1;
    const int warp_n = wid >> 1;

    const int z = (mode == 3) ? 3 : (int)blockIdx.z;
    const __nv_bfloat16* Ah = (mode == 3) ? g_ah : g_xh;
    const __nv_bfloat16* Al = (mode == 3) ? g_al : g_xl;
    const __nv_bfloat16* Bh = g_wh[z];
    const __nv_bfloat16* Bl = g_wl[z];

    const int tm = blockIdx.y;
    const int tn = blockIdx.x;

    const __nv_bfloat16* srcs[4] = {
        Ah + (size_t)(tm * 128) * DM,
        Al + (size_t)(tm * 128) * DM,
        Bh + (size_t)(tn * 128) * DM,
        Bl + (size_t)(tn * 128) * DM };

    // ldmatrix fragment lane mapping (validated)
    const int a_row = warp_m * 64 + (lane & 15);
    const int a_col = (lane >> 4) << 3;
    const int bgrp  = lane >> 3;
    const int b_row = warp_n * 32 + ((bgrp >= 2) ? 8 : 0) + (lane & 7);
    const int b_col = (bgrp & 1) << 3;

    // staging mapping: thread -> (row, 16B segment)
    const int seg   = (tid & 3) << 3;    // col in bf16 (0,8,16,24)
    const int rbase = tid >> 2;          // 0..63

    float acc[4][4][4];
#pragma unroll
    for (int i = 0; i < 4; i++)
#pragma unroll
        for (int j = 0; j < 4; j++)
#pragma unroll
            for (int k = 0; k < 4; k++) acc[i][j][k] = 0.f;

    auto stage = [&](int kc, int buf) {
#pragma unroll
        for (int tile = 0; tile < 4; tile++) {
#pragma unroll
            for (int half = 0; half < 2; half++) {
                const int r = rbase + half * 64;
                cpasync16(dsm_u + (uint32_t)(((buf * 4 + tile) * TILE_ELEMS) + r * ASTR + seg) * 2,
                          srcs[tile] + (size_t)r * DM + kc * 32 + seg);
            }
        }
        asm volatile("cp.async.commit_group;" ::: "memory");
    };

    stage(0, 0);

    int buf = 0;
    for (int kc = 0; kc < 32; kc++) {
        if (kc < 31) {
            stage(kc + 1, buf ^ 1);
            asm volatile("cp.async.wait_group 1;" ::: "memory");
        } else {
            asm volatile("cp.async.wait_group 0;" ::: "memory");
        }
        __syncthreads();

        const uint32_t sAh_u = dsm_u + (uint32_t)((buf * 4 + 0) * TILE_ELEMS) * 2;
        const uint32_t sAl_u = dsm_u + (uint32_t)((buf * 4 + 1) * TILE_ELEMS) * 2;
        const uint32_t sBh_u = dsm_u + (uint32_t)((buf * 4 + 2) * TILE_ELEMS) * 2;
        const uint32_t sBl_u = dsm_u + (uint32_t)((buf * 4 + 3) * TILE_ELEMS) * 2;

#pragma unroll
        for (int ks = 0; ks < 2; ks++) {
            uint32_t ah4[4][4], al4[4][4], bh4[2][4], bl4[2][4];
#pragma unroll
            for (int mt = 0; mt < 4; mt++) {
                const uint32_t ro = (uint32_t)((a_row + mt * 16) * ASTR + ks * 16 + a_col) * 2;
                ldsm4(ah4[mt], sAh_u + ro);
                ldsm4(al4[mt], sAl_u + ro);
            }
#pragma unroll
            for (int np = 0; np < 2; np++) {
                const uint32_t ro = (uint32_t)((b_row + np * 16) * ASTR + ks * 16 + b_col) * 2;
                ldsm4(bh4[np], sBh_u + ro);
                ldsm4(bl4[np], sBl_u + ro);
            }
#pragma unroll
            for (int mt = 0; mt < 4; mt++)
#pragma unroll
                for (int nt = 0; nt < 4; nt++)
                    mma16816(acc[mt][nt], ah4[mt], &bh4[nt >> 1][(nt & 1) * 2]);
#pragma unroll
            for (int mt = 0; mt < 4; mt++)
#pragma unroll
                for (int nt = 0; nt < 4; nt++)
                    mma16816(acc[mt][nt], al4[mt], &bh4[nt >> 1][(nt & 1) * 2]);
#pragma unroll
            for (int mt = 0; mt < 4; mt++)
#pragma unroll
                for (int nt = 0; nt < 4; nt++)
                    mma16816(acc[mt][nt], ah4[mt], &bl4[nt >> 1][(nt & 1) * 2]);
        }
        __syncthreads();
        buf ^= 1;
    }

    const int dr = lane >> 2, dc = (lane & 3) << 1;
    const int mbase = tm * 128 + warp_m * 64;
    const int nbase = tn * 128 + warp_n * 32;

    if (mode == 3) {
        float* Yp = outp + (size_t)mbase * DM + nbase;
#pragma unroll
        for (int mt = 0; mt < 4; mt++)
#pragma unroll
            for (int nt = 0; nt < 4; nt++) {
                *(float2*)&Yp[(size_t)(mt * 16 + dr) * DM + nt * 8 + dc] =
                    make_float2(acc[mt][nt][0], acc[mt][nt][1]);
                *(float2*)&Yp[(size_t)(mt * 16 + 8 + dr) * DM + nt * 8 + dc] =
                    make_float2(acc[mt][nt][2], acc[mt][nt][3]);
            }
    } else {
        __nv_bfloat16* Yh = (z == 0) ? g_qh : (z == 1 ? g_kh : g_vh);
        __nv_bfloat16* Yl = (z == 0) ? g_ql : (z == 1 ? g_kl : g_vl);
#pragma unroll
        for (int mt = 0; mt < 4; mt++)
#pragma unroll
            for (int nt = 0; nt < 4; nt++) {
#pragma unroll
                for (int half = 0; half < 2; half++) {
                    const float va = acc[mt][nt][half * 2];
                    const float vb = acc[mt][nt][half * 2 + 1];
                    const __nv_bfloat16 ha = __float2bfloat16(va);
                    const __nv_bfloat16 hb = __float2bfloat16(vb);
                    const size_t off = (size_t)(mbase + mt * 16 + half * 8 + dr) * DM
                                       + nbase + nt * 8 + dc;
                    __nv_bfloat162 hp = __halves2bfloat162(ha, hb);
                    *(uint32_t*)&Yh[off] = *(uint32_t*)&hp;
                    *(uint32_t*)&Yl[off] =
                        packbf(va - __bfloat162float(ha), vb - __bfloat162float(hb));
                }
            }
    }
}

// ---------------------------------------------------------------------------
// Flash attention (FA2-style, HMMA) — unchanged from round 12 (known-good).
// ---------------------------------------------------------------------------
#define KSTR 72

__global__ __launch_bounds__(256) void attn_kernel()
{
    __shared__ __nv_bfloat16 sKh[64 * KSTR], sKl[64 * KSTR];
    __shared__ __nv_bfloat16 sVh[64 * KSTR], sVl[64 * KSTR];

    const int tid  = threadIdx.x;
    const int lane = tid & 31;
    const int w    = tid >> 5;
    const int xb   = gridDim.x - 1 - blockIdx.x;
    const int q0   = xb * 128;
    const int h    = blockIdx.y;
    const int b    = blockIdx.z;

    const int r0g  = q0 + w * 16 + (lane >> 2);
    const int r1g  = r0g + 8;
    const int qcol = (lane & 3) << 1;

    const uint32_t sKh_u = smem_u32(sKh), sKl_u = smem_u32(sKl);
    const uint32_t sVh_u = smem_u32(sVh), sVl_u = smem_u32(sVl);

    const int kb_row = ((lane >> 4) & 1) * 8 + (lane & 7);
    const int kb_col = ((lane >> 3) & 1) * 8;
    const int vt_k = ((lane >> 3) & 1) * 8 + (lane & 7);
    const int vt_n = (lane >> 4) * 8;

    uint32_t qh[4][4], ql[4][4];
    {
        const size_t base0 = (size_t)(b * TSEQ + r0g) * DM + h * HD;
        const size_t base1 = (size_t)(b * TSEQ + r1g) * DM + h * HD;
#pragma unroll
        for (int ks = 0; ks < 4; ks++) {
            qh[ks][0] = *(const uint32_t*)&g_qh[base0 + ks * 16 + qcol];
            qh[ks][1] = *(const uint32_t*)&g_qh[base1 + ks * 16 + qcol];
            qh[ks][2] = *(const uint32_t*)&g_qh[base0 + ks * 16 + 8 + qcol];
            qh[ks][3] = *(const uint32_t*)&g_qh[base1 + ks * 16 + 8 + qcol];
            ql[ks][0] = *(const uint32_t*)&g_ql[base0 + ks * 16 + qcol];
            ql[ks][1] = *(const uint32_t*)&g_ql[base1 + ks * 16 + qcol];
            ql[ks][2] = *(const uint32_t*)&g_ql[base0 + ks * 16 + 8 + qcol];
            ql[ks][3] = *(const uint32_t*)&g_ql[base1 + ks * 16 + 8 + qcol];
        }
    }

    float O[8][4];
#pragma unroll
    for (int i = 0; i < 8; i++)
#pragma unroll
        for (int j = 0; j < 4; j++) O[i][j] = 0.f;
    float m0 = -1e30f, m1 = -1e30f, l0 = 0.f, l1 = 0.f;

    const int ntiles = 2 * xb + 2;
    for (int t = 0; t < ntiles; t++) {
        __syncthreads();
#pragma unroll
        for (int i = 0; i < 2; i++) {
            const int li = tid + i * 256;
            const int row = li >> 3, ch = (li & 7) << 3;
            const size_t g = (size_t)(b * TSEQ + t * 64 + row) * DM + h * HD + ch;
            const int so = row * KSTR + ch;
            *(uint4*)&sKh[so] = *(const uint4*)&g_kh[g];
            *(uint4*)&sKl[so] = *(const uint4*)&g_kl[g];
            *(uint4*)&sVh[so] = *(const uint4*)&g_vh[g];
            *(uint4*)&sVl[so] = *(const uint4*)&g_vl[g];
        }
        __syncthreads();

        float s[8][4];
#pragma unroll
        for (int i = 0; i < 8; i++)
#pragma unroll
            for (int j = 0; j < 4; j++) s[i][j] = 0.f;

#pragma unroll
        for (int ks = 0; ks < 4; ks++) {
#pragma unroll
            for (int np = 0; np < 4; np++) {
                uint32_t kh4[4], kl4[4];
                const uint32_t off =
                    (uint32_t)((np * 16 + kb_row) * KSTR + ks * 16 + kb_col) * 2;
                ldsm4(kh4, sKh_u + off);
                ldsm4(kl4, sKl_u + off);
                mma16816(s[np * 2],     qh[ks], &kh4[0]);
                mma16816(s[np * 2 + 1], qh[ks], &kh4[2]);
                mma16816(s[np * 2],     ql[ks], &kh4[0]);
                mma16816(s[np * 2 + 1], ql[ks], &kh4[2]);
                mma16816(s[np * 2],     qh[ks], &kl4[0]);
                mma16816(s[np * 2 + 1], qh[ks], &kl4[2]);
            }
        }

        const bool masked = (t >= 2 * xb);
#pragma unroll
        for (int nt = 0; nt < 8; nt++)
#pragma unroll
            for (int e = 0; e < 4; e++) {
                float v = s[nt][e] * 0.125f;
                if (masked) {
                    const int col = t * 64 + nt * 8 + qcol + (e & 1);
                    const int row = (e < 2) ? r0g : r1g;
                    if (col > row) v = -1e30f;
                }
                s[nt][e] = v;
            }

        float mx0 = -1e30f, mx1 = -1e30f;
#pragma unroll
        for (int nt = 0; nt < 8; nt++) {
            mx0 = fmaxf(mx0, fmaxf(s[nt][0], s[nt][1]));
            mx1 = fmaxf(mx1, fmaxf(s[nt][2], s[nt][3]));
        }
        mx0 = fmaxf(mx0, __shfl_xor_sync(0xffffffffu, mx0, 1));
        mx0 = fmaxf(mx0, __shfl_xor_sync(0xffffffffu, mx0, 2));
        mx1 = fmaxf(mx1, __shfl_xor_sync(0xffffffffu, mx1, 1));
        mx1 = fmaxf(mx1, __shfl_xor_sync(0xffffffffu, mx1, 2));

        const float mn0 = fmaxf(m0, mx0);
        const float mn1 = fmaxf(m1, mx1);
        const float corr0 = __expf(m0 - mn0);
        const float corr1 = __expf(m1 - mn1);
        m0 = mn0; m1 = mn1;

        uint32_t ph[4][4], pl[4][4];
        float sum0 = 0.f, sum1 = 0.f;
#pragma unroll
        for (int nt = 0; nt < 8; nt++) {
            const int ks = nt >> 1, ro = (nt & 1) * 2;
            const float p0 = __expf(s[nt][0] - mn0);
            const float p1 = __expf(s[nt][1] - mn0);
            const float p2 = __expf(s[nt][2] - mn1);
            const float p3 = __expf(s[nt][3] - mn1);
            sum0 += p0 + p1; sum1 += p2 + p3;
            const __nv_bfloat16 h0 = __float2bfloat16(p0);
            const __nv_bfloat16 h1 = __float2bfloat16(p1);
            const __nv_bfloat16 h2 = __float2bfloat16(p2);
            const __nv_bfloat16 h3 = __float2bfloat16(p3);
            __nv_bfloat162 t01 = __halves2bfloat162(h0, h1);
            __nv_bfloat162 t23 = __halves2bfloat162(h2, h3);
            ph[ks][ro]     = *(uint32_t*)&t01;
            ph[ks][ro + 1] = *(uint32_t*)&t23;
            pl[ks][ro]     = packbf(p0 - __bfloat162float(h0), p1 - __bfloat162float(h1));
            pl[ks][ro + 1] = packbf(p2 - __bfloat162float(h2), p3 - __bfloat162float(h3));
        }
        sum0 += __shfl_xor_sync(0xffffffffu, sum0, 1);
        sum0 += __shfl_xor_sync(0xffffffffu, sum0, 2);
        sum1 += __shfl_xor_sync(0xffffffffu, sum1, 1);
        sum1 += __shfl_xor_sync(0xffffffffu, sum1, 2);
        l0 = l0 * corr0 + sum0;
        l1 = l1 * corr1 + sum1;

#pragma unroll
        for (int nt = 0; nt < 8; nt++) {
            O[nt][0] *= corr0; O[nt][1] *= corr0;
            O[nt][2] *= corr1; O[nt][3] *= corr1;
        }

#pragma unroll
        for (int ks = 0; ks < 4; ks++) {
#pragma unroll
            for (int np = 0; np < 4; np++) {
                uint32_t vh4[4], vl4[4];
                const uint32_t off =
                    (uint32_t)((ks * 16 + vt_k) * KSTR + np * 16 + vt_n) * 2;
                ldsm4t(vh4, sVh_u + off);
                ldsm4t(vl4, sVl_u + off);
                mma16816(O[np * 2],     ph[ks], &vh4[0]);
                mma16816(O[np * 2 + 1], ph[ks], &vh4[2]);
                mma16816(O[np * 2],     pl[ks], &vh4[0]);
                mma16816(O[np * 2 + 1], pl[ks], &vh4[2]);
                mma16816(O[np * 2],     ph[ks], &vl4[0]);
                mma16816(O[np * 2 + 1], ph[ks], &vl4[2]);
            }
        }
    }

    const float inv0 = 1.f / l0;
    const float inv1 = 1.f / l1;
    const size_t ob0 = (size_t)(b * TSEQ + r0g) * DM + h * HD;
    const size_t ob1 = (size_t)(b * TSEQ + r1g) * DM + h * HD;
#pragma unroll
    for (int nt = 0; nt < 8; nt++) {
        const float v0 = O[nt][0] * inv0, v1 = O[nt][1] * inv0;
        const float v2 = O[nt][2] * inv1, v3 = O[nt][3] * inv1;
        const __nv_bfloat16 h0 = __float2bfloat16(v0);
        const __nv_bfloat16 h1 = __float2bfloat16(v1);
        const __nv_bfloat16 h2 = __float2bfloat16(v2);
        const __nv_bfloat16 h3 = __float2bfloat16(v3);
        __nv_bfloat162 t01 = __halves2bfloat162(h0, h1);
        __nv_bfloat162 t23 = __halves2bfloat162(h2, h3);
        *(uint32_t*)&g_ah[ob0 + nt * 8 + qcol] = *(uint32_t*)&t01;
        *(uint32_t*)&g_ah[ob1 + nt * 8 + qcol] = *(uint32_t*)&t23;
        *(uint32_t*)&g_al[ob0 + nt * 8 + qcol] =
            packbf(v0 - __bfloat162float(h0), v1 - __bfloat162float(h1));
        *(uint32_t*)&g_al[ob1 + nt * 8 + qcol] =
            packbf(v2 - __bfloat162float(h2), v3 - __bfloat162float(h3));
    }
}

// ---------------------------------------------------------------------------
extern "C" void kernel_launch(void* const* d_in, const int* in_sizes, int n_in,
                              void* d_out, int out_size)
{
    const float* x  = (const float*)d_in[0];
    const float* Wq = (const float*)d_in[1];
    const float* Wk = (const float*)d_in[2];
    const float* Wv = (const float*)d_in[3];
    const float* Wo = (const float*)d_in[4];
    float* out = (float*)d_out;

    cudaFuncSetAttribute(tgemm_kernel,
                         cudaFuncAttributeMaxDynamicSharedMemorySize, GSMEM_BYTES);

    const int total4 = XN4 + 4 * WN4;
    split_all<<<(total4 + 255) / 256, 256>>>(x, Wq, Wk, Wv, Wo);

    dim3 gq(DM / 128, MR / 128, 3);
    tgemm_kernel<<<gq, 256, GSMEM_BYTES>>>(0, nullptr);

    dim3 ga(TSEQ / 128, NH, BB);
    attn_kernel<<<ga, 256>>>();

    dim3 gp(DM / 128, MR / 128, 1);
    tgemm_kernel<<<gp, 256, GSMEM_BYTES>>>(3, out);
}

// round 16
// speedup vs baseline: 4.4415x; 1.0760x over previous
#include <cuda_runtime.h>
#include <cuda_bf16.h>
#include <cstdint>

#define TSEQ 2048
#define BB 2
#define DM 1024
#define NH 16
#define HD 64
#define MR (BB*TSEQ)   // 4096 rows

// ---------------------------------------------------------------------------
// Scratch (allocation-free rule: __device__ globals) — all bf16 hi/lo pairs
// ---------------------------------------------------------------------------
__device__ __nv_bfloat16 g_xh[(size_t)MR * DM];
__device__ __nv_bfloat16 g_xl[(size_t)MR * DM];
__device__ __nv_bfloat16 g_qh[(size_t)MR * DM];
__device__ __nv_bfloat16 g_ql[(size_t)MR * DM];
__device__ __nv_bfloat16 g_kh[(size_t)MR * DM];
__device__ __nv_bfloat16 g_kl[(size_t)MR * DM];
__device__ __nv_bfloat16 g_vh[(size_t)MR * DM];
__device__ __nv_bfloat16 g_vl[(size_t)MR * DM];
__device__ __nv_bfloat16 g_ah[(size_t)MR * DM];
__device__ __nv_bfloat16 g_al[(size_t)MR * DM];
__device__ __nv_bfloat16 g_wh[4][(size_t)DM * DM];
__device__ __nv_bfloat16 g_wl[4][(size_t)DM * DM];

// ---------------------------------------------------------------------------
// Warp MMA helpers (base-ISA: ldmatrix + mma.sync + cp.async)
// ---------------------------------------------------------------------------
__device__ __forceinline__ uint32_t smem_u32(const void* p) {
    uint32_t a;
    asm("{ .reg .u64 t; cvta.to.shared.u64 t, %1; cvt.u32.u64 %0, t; }" : "=r"(a) : "l"(p));
    return a;
}
__device__ __forceinline__ void ldsm4(uint32_t (&r)[4], uint32_t addr) {
    asm volatile("ldmatrix.sync.aligned.m8n8.x4.shared.b16 {%0,%1,%2,%3}, [%4];"
                 : "=r"(r[0]), "=r"(r[1]), "=r"(r[2]), "=r"(r[3]) : "r"(addr));
}
__device__ __forceinline__ void ldsm4t(uint32_t (&r)[4], uint32_t addr) {
    asm volatile("ldmatrix.sync.aligned.m8n8.x4.trans.shared.b16 {%0,%1,%2,%3}, [%4];"
                 : "=r"(r[0]), "=r"(r[1]), "=r"(r[2]), "=r"(r[3]) : "r"(addr));
}
__device__ __forceinline__ void mma16816(float* c, const uint32_t* a, const uint32_t* b) {
    asm volatile("mma.sync.aligned.m16n8k16.row.col.f32.bf16.bf16.f32 "
                 "{%0,%1,%2,%3},{%4,%5,%6,%7},{%8,%9},{%0,%1,%2,%3};"
                 : "+f"(c[0]), "+f"(c[1]), "+f"(c[2]), "+f"(c[3])
                 : "r"(a[0]), "r"(a[1]), "r"(a[2]), "r"(a[3]), "r"(b[0]), "r"(b[1]));
}
__device__ __forceinline__ uint32_t packbf(float a, float b) {
    __nv_bfloat162 t = __floats2bfloat162_rn(a, b);
    return *(uint32_t*)&t;
}
__device__ __forceinline__ void cpasync16(uint32_t saddr, const void* g) {
    asm volatile("cp.async.cg.shared.global [%0], [%1], 16;" :: "r"(saddr), "l"(g) : "memory");
}

// ---------------------------------------------------------------------------
// Fused fp32 -> bf16 hi/lo split for x and all four weights in ONE launch.
// ---------------------------------------------------------------------------
#define XN4 ((MR * DM) / 4)    // 1,048,576
#define WN4 ((DM * DM) / 4)    // 262,144 = 2^18

__global__ __launch_bounds__(256) void split_all(const float* __restrict__ x,
                                                 const float* __restrict__ Wq,
                                                 const float* __restrict__ Wk,
                                                 const float* __restrict__ Wv,
                                                 const float* __restrict__ Wo)
{
    const int i = blockIdx.x * 256 + threadIdx.x;
    const float* s;
    __nv_bfloat16 *h, *l;
    int j;
    if (i < XN4) { s = x; h = g_xh; l = g_xl; j = i; }
    else {
        const int k = i - XN4;
        const int w = k >> 18;
        j = k & (WN4 - 1);
        s = (w == 0) ? Wq : (w == 1) ? Wk : (w == 2) ? Wv : Wo;
        h = g_wh[w]; l = g_wl[w];
    }
    const float4 v = ((const float4*)s)[j];
    const __nv_bfloat16 h0 = __float2bfloat16(v.x);
    const __nv_bfloat16 h1 = __float2bfloat16(v.y);
    const __nv_bfloat16 h2 = __float2bfloat16(v.z);
    const __nv_bfloat16 h3 = __float2bfloat16(v.w);
    ((__nv_bfloat162*)h)[2 * j]     = __halves2bfloat162(h0, h1);
    ((__nv_bfloat162*)h)[2 * j + 1] = __halves2bfloat162(h2, h3);
    *(uint32_t*)&((__nv_bfloat162*)l)[2 * j]     = packbf(v.x - __bfloat162float(h0), v.y - __bfloat162float(h1));
    *(uint32_t*)&((__nv_bfloat162*)l)[2 * j + 1] = packbf(v.z - __bfloat162float(h2), v.w - __bfloat162float(h3));
}

// ---------------------------------------------------------------------------
// Tensor-core GEMM (HMMA): unchanged from round 14 (known-good).
// ---------------------------------------------------------------------------
#define ASTR 40
#define TILE_ELEMS (128 * ASTR)           // 5120 bf16
#define GSMEM_BYTES (8 * TILE_ELEMS * 2)  // 81920

__global__ __launch_bounds__(256) void tgemm_kernel(int mode, float* __restrict__ outp)
{
    extern __shared__ __nv_bfloat16 dsm[];
    const uint32_t dsm_u = smem_u32(dsm);

    const int tid  = threadIdx.x;
    const int lane = tid & 31;
    const int wid  = tid >> 5;
    const int warp_m = wid & 1;
    const int warp_n = wid >> 1;

    const int z = (mode == 3) ? 3 : (int)blockIdx.z;
    const __nv_bfloat16* Ah = (mode == 3) ? g_ah : g_xh;
    const __nv_bfloat16* Al = (mode == 3) ? g_al : g_xl;
    const __nv_bfloat16* Bh = g_wh[z];
    const __nv_bfloat16* Bl = g_wl[z];

    const int tm = blockIdx.y;
    const int tn = blockIdx.x;

    const __nv_bfloat16* srcs[4] = {
        Ah + (size_t)(tm * 128) * DM,
        Al + (size_t)(tm * 128) * DM,
        Bh + (size_t)(tn * 128) * DM,
        Bl + (size_t)(tn * 128) * DM };

    const int a_row = warp_m * 64 + (lane & 15);
    const int a_col = (lane >> 4) << 3;
    const int bgrp  = lane >> 3;
    const int b_row = warp_n * 32 + ((bgrp >= 2) ? 8 : 0) + (lane & 7);
    const int b_col = (bgrp & 1) << 3;

    const int seg   = (tid & 3) << 3;
    const int rbase = tid >> 2;

    float acc[4][4][4];
#pragma unroll
    for (int i = 0; i < 4; i++)
#pragma unroll
        for (int j = 0; j < 4; j++)
#pragma unroll
            for (int k = 0; k < 4; k++) acc[i][j][k] = 0.f;

    auto stage = [&](int kc, int buf) {
#pragma unroll
        for (int tile = 0; tile < 4; tile++) {
#pragma unroll
            for (int half = 0; half < 2; half++) {
                const int r = rbase + half * 64;
                cpasync16(dsm_u + (uint32_t)(((buf * 4 + tile) * TILE_ELEMS) + r * ASTR + seg) * 2,
                          srcs[tile] + (size_t)r * DM + kc * 32 + seg);
            }
        }
        asm volatile("cp.async.commit_group;" ::: "memory");
    };

    stage(0, 0);

    int buf = 0;
    for (int kc = 0; kc < 32; kc++) {
        if (kc < 31) {
            stage(kc + 1, buf ^ 1);
            asm volatile("cp.async.wait_group 1;" ::: "memory");
        } else {
            asm volatile("cp.async.wait_group 0;" ::: "memory");
        }
        __syncthreads();

        const uint32_t sAh_u = dsm_u + (uint32_t)((buf * 4 + 0) * TILE_ELEMS) * 2;
        const uint32_t sAl_u = dsm_u + (uint32_t)((buf * 4 + 1) * TILE_ELEMS) * 2;
        const uint32_t sBh_u = dsm_u + (uint32_t)((buf * 4 + 2) * TILE_ELEMS) * 2;
        const uint32_t sBl_u = dsm_u + (uint32_t)((buf * 4 + 3) * TILE_ELEMS) * 2;

#pragma unroll
        for (int ks = 0; ks < 2; ks++) {
            uint32_t ah4[4][4], al4[4][4], bh4[2][4], bl4[2][4];
#pragma unroll
            for (int mt = 0; mt < 4; mt++) {
                const uint32_t ro = (uint32_t)((a_row + mt * 16) * ASTR + ks * 16 + a_col) * 2;
                ldsm4(ah4[mt], sAh_u + ro);
                ldsm4(al4[mt], sAl_u + ro);
            }
#pragma unroll
            for (int np = 0; np < 2; np++) {
                const uint32_t ro = (uint32_t)((b_row + np * 16) * ASTR + ks * 16 + b_col) * 2;
                ldsm4(bh4[np], sBh_u + ro);
                ldsm4(bl4[np], sBl_u + ro);
            }
#pragma unroll
            for (int mt = 0; mt < 4; mt++)
#pragma unroll
                for (int nt = 0; nt < 4; nt++)
                    mma16816(acc[mt][nt], ah4[mt], &bh4[nt >> 1][(nt & 1) * 2]);
#pragma unroll
            for (int mt = 0; mt < 4; mt++)
#pragma unroll
                for (int nt = 0; nt < 4; nt++)
                    mma16816(acc[mt][nt], al4[mt], &bh4[nt >> 1][(nt & 1) * 2]);
#pragma unroll
            for (int mt = 0; mt < 4; mt++)
#pragma unroll
                for (int nt = 0; nt < 4; nt++)
                    mma16816(acc[mt][nt], ah4[mt], &bl4[nt >> 1][(nt & 1) * 2]);
        }
        __syncthreads();
        buf ^= 1;
    }

    const int dr = lane >> 2, dc = (lane & 3) << 1;
    const int mbase = tm * 128 + warp_m * 64;
    const int nbase = tn * 128 + warp_n * 32;

    if (mode == 3) {
        float* Yp = outp + (size_t)mbase * DM + nbase;
#pragma unroll
        for (int mt = 0; mt < 4; mt++)
#pragma unroll
            for (int nt = 0; nt < 4; nt++) {
                *(float2*)&Yp[(size_t)(mt * 16 + dr) * DM + nt * 8 + dc] =
                    make_float2(acc[mt][nt][0], acc[mt][nt][1]);
                *(float2*)&Yp[(size_t)(mt * 16 + 8 + dr) * DM + nt * 8 + dc] =
                    make_float2(acc[mt][nt][2], acc[mt][nt][3]);
            }
    } else {
        __nv_bfloat16* Yh = (z == 0) ? g_qh : (z == 1 ? g_kh : g_vh);
        __nv_bfloat16* Yl = (z == 0) ? g_ql : (z == 1 ? g_kl : g_vl);
#pragma unroll
        for (int mt = 0; mt < 4; mt++)
#pragma unroll
            for (int nt = 0; nt < 4; nt++) {
#pragma unroll
                for (int half = 0; half < 2; half++) {
                    const float va = acc[mt][nt][half * 2];
                    const float vb = acc[mt][nt][half * 2 + 1];
                    const __nv_bfloat16 ha = __float2bfloat16(va);
                    const __nv_bfloat16 hb = __float2bfloat16(vb);
                    const size_t off = (size_t)(mbase + mt * 16 + half * 8 + dr) * DM
                                       + nbase + nt * 8 + dc;
                    __nv_bfloat162 hp = __halves2bfloat162(ha, hb);
                    *(uint32_t*)&Yh[off] = *(uint32_t*)&hp;
                    *(uint32_t*)&Yl[off] =
                        packbf(va - __bfloat162float(ha), vb - __bfloat162float(hb));
                }
            }
    }
}

// ---------------------------------------------------------------------------
// Flash attention (FA2-style, HMMA) with cp.async double-buffered K/V tiles.
// Grid (16, NH, BB), 256 threads = 8 warps; warp owns 16 q-rows.
// ---------------------------------------------------------------------------
#define KSTR 72
#define KVTILE_B (64 * KSTR * 2)               // 9216 bytes per sub-tile
#define ATT_SMEM (2 * 4 * KVTILE_B)            // 73728 bytes (2 stages)

__global__ __launch_bounds__(256) void attn_kernel()
{
    extern __shared__ char asm_raw[];
    const uint32_t dsm_u = smem_u32(asm_raw);

    const int tid  = threadIdx.x;
    const int lane = tid & 31;
    const int w    = tid >> 5;
    const int xb   = gridDim.x - 1 - blockIdx.x;   // heavy blocks first
    const int q0   = xb * 128;
    const int h    = blockIdx.y;
    const int b    = blockIdx.z;

    const int r0g  = q0 + w * 16 + (lane >> 2);
    const int r1g  = r0g + 8;
    const int qcol = (lane & 3) << 1;

    const int kb_row = ((lane >> 4) & 1) * 8 + (lane & 7);
    const int kb_col = ((lane >> 3) & 1) * 8;
    const int vt_k = ((lane >> 3) & 1) * 8 + (lane & 7);
    const int vt_n = (lane >> 4) * 8;

    uint32_t qh[4][4], ql[4][4];
    {
        const size_t base0 = (size_t)(b * TSEQ + r0g) * DM + h * HD;
        const size_t base1 = (size_t)(b * TSEQ + r1g) * DM + h * HD;
#pragma unroll
        for (int ks = 0; ks < 4; ks++) {
            qh[ks][0] = *(const uint32_t*)&g_qh[base0 + ks * 16 + qcol];
            qh[ks][1] = *(const uint32_t*)&g_qh[base1 + ks * 16 + qcol];
            qh[ks][2] = *(const uint32_t*)&g_qh[base0 + ks * 16 + 8 + qcol];
            qh[ks][3] = *(const uint32_t*)&g_qh[base1 + ks * 16 + 8 + qcol];
            ql[ks][0] = *(const uint32_t*)&g_ql[base0 + ks * 16 + qcol];
            ql[ks][1] = *(const uint32_t*)&g_ql[base1 + ks * 16 + qcol];
            ql[ks][2] = *(const uint32_t*)&g_ql[base0 + ks * 16 + 8 + qcol];
            ql[ks][3] = *(const uint32_t*)&g_ql[base1 + ks * 16 + 8 + qcol];
        }
    }

    float O[8][4];
#pragma unroll
    for (int i = 0; i < 8; i++)
#pragma unroll
        for (int j = 0; j < 4; j++) O[i][j] = 0.f;
    float m0 = -1e30f, m1 = -1e30f, l0 = 0.f, l1 = 0.f;

    // cp.async staging of the 4 K/V sub-tiles of tile t into stage bufi
    auto stageKV = [&](int t, int bufi) {
#pragma unroll
        for (int i = 0; i < 2; i++) {
            const int li = tid + i * 256;
            const int row = li >> 3, ch = (li & 7) << 3;
            const size_t g = (size_t)(b * TSEQ + t * 64 + row) * DM + h * HD + ch;
            const uint32_t so = dsm_u + (uint32_t)(bufi * 4 * KVTILE_B)
                              + (uint32_t)(row * KSTR + ch) * 2;
            cpasync16(so,                 &g_kh[g]);
            cpasync16(so + KVTILE_B,      &g_kl[g]);
            cpasync16(so + 2 * KVTILE_B,  &g_vh[g]);
            cpasync16(so + 3 * KVTILE_B,  &g_vl[g]);
        }
        asm volatile("cp.async.commit_group;" ::: "memory");
    };

    const int ntiles = 2 * xb + 2;
    stageKV(0, 0);

    int bufi = 0;
    for (int t = 0; t < ntiles; t++) {
        if (t + 1 < ntiles) {
            stageKV(t + 1, bufi ^ 1);
            asm volatile("cp.async.wait_group 1;" ::: "memory");
        } else {
            asm volatile("cp.async.wait_group 0;" ::: "memory");
        }
        __syncthreads();

        const uint32_t sKh_u = dsm_u + (uint32_t)(bufi * 4 * KVTILE_B);
        const uint32_t sKl_u = sKh_u + KVTILE_B;
        const uint32_t sVh_u = sKh_u + 2 * KVTILE_B;
        const uint32_t sVl_u = sKh_u + 3 * KVTILE_B;

        float s[8][4];
#pragma unroll
        for (int i = 0; i < 8; i++)
#pragma unroll
            for (int j = 0; j < 4; j++) s[i][j] = 0.f;

#pragma unroll
        for (int ks = 0; ks < 4; ks++) {
#pragma unroll
            for (int np = 0; np < 4; np++) {
                uint32_t kh4[4], kl4[4];
                const uint32_t off =
                    (uint32_t)((np * 16 + kb_row) * KSTR + ks * 16 + kb_col) * 2;
                ldsm4(kh4, sKh_u + off);
                ldsm4(kl4, sKl_u + off);
                mma16816(s[np * 2],     qh[ks], &kh4[0]);
                mma16816(s[np * 2 + 1], qh[ks], &kh4[2]);
                mma16816(s[np * 2],     ql[ks], &kh4[0]);
                mma16816(s[np * 2 + 1], ql[ks], &kh4[2]);
                mma16816(s[np * 2],     qh[ks], &kl4[0]);
                mma16816(s[np * 2 + 1], qh[ks], &kl4[2]);
            }
        }

        const bool masked = (t >= 2 * xb);
#pragma unroll
        for (int nt = 0; nt < 8; nt++)
#pragma unroll
            for (int e = 0; e < 4; e++) {
                float v = s[nt][e] * 0.125f;
                if (masked) {
                    const int col = t * 64 + nt * 8 + qcol + (e & 1);
                    const int row = (e < 2) ? r0g : r1g;
                    if (col > row) v = -1e30f;
                }
                s[nt][e] = v;
            }

        float mx0 = -1e30f, mx1 = -1e30f;
#pragma unroll
        for (int nt = 0; nt < 8; nt++) {
            mx0 = fmaxf(mx0, fmaxf(s[nt][0], s[nt][1]));
            mx1 = fmaxf(mx1, fmaxf(s[nt][2], s[nt][3]));
        }
        mx0 = fmaxf(mx0, __shfl_xor_sync(0xffffffffu, mx0, 1));
        mx0 = fmaxf(mx0, __shfl_xor_sync(0xffffffffu, mx0, 2));
        mx1 = fmaxf(mx1, __shfl_xor_sync(0xffffffffu, mx1, 1));
        mx1 = fmaxf(mx1, __shfl_xor_sync(0xffffffffu, mx1, 2));

        const float mn0 = fmaxf(m0, mx0);
        const float mn1 = fmaxf(m1, mx1);
        const float corr0 = __expf(m0 - mn0);
        const float corr1 = __expf(m1 - mn1);
        m0 = mn0; m1 = mn1;

        uint32_t ph[4][4], pl[4][4];
        float sum0 = 0.f, sum1 = 0.f;
#pragma unroll
        for (int nt = 0; nt < 8; nt++) {
            const int ks = nt >> 1, ro = (nt & 1) * 2;
            const float p0 = __expf(s[nt][0] - mn0);
            const float p1 = __expf(s[nt][1] - mn0);
            const float p2 = __expf(s[nt][2] - mn1);
            const float p3 = __expf(s[nt][3] - mn1);
            sum0 += p0 + p1; sum1 += p2 + p3;
            const __nv_bfloat16 h0 = __float2bfloat16(p0);
            const __nv_bfloat16 h1 = __float2bfloat16(p1);
            const __nv_bfloat16 h2 = __float2bfloat16(p2);
            const __nv_bfloat16 h3 = __float2bfloat16(p3);
            __nv_bfloat162 t01 = __halves2bfloat162(h0, h1);
            __nv_bfloat162 t23 = __halves2bfloat162(h2, h3);
            ph[ks][ro]     = *(uint32_t*)&t01;
            ph[ks][ro + 1] = *(uint32_t*)&t23;
            pl[ks][ro]     = packbf(p0 - __bfloat162float(h0), p1 - __bfloat162float(h1));
            pl[ks][ro + 1] = packbf(p2 - __bfloat162float(h2), p3 - __bfloat162float(h3));
        }
        sum0 += __shfl_xor_sync(0xffffffffu, sum0, 1);
        sum0 += __shfl_xor_sync(0xffffffffu, sum0, 2);
        sum1 += __shfl_xor_sync(0xffffffffu, sum1, 1);
        sum1 += __shfl_xor_sync(0xffffffffu, sum1, 2);
        l0 = l0 * corr0 + sum0;
        l1 = l1 * corr1 + sum1;

#pragma unroll
        for (int nt = 0; nt < 8; nt++) {
            O[nt][0] *= corr0; O[nt][1] *= corr0;
            O[nt][2] *= corr1; O[nt][3] *= corr1;
        }

#pragma unroll
        for (int ks = 0; ks < 4; ks++) {
#pragma unroll
            for (int np = 0; np < 4; np++) {
                uint32_t vh4[4], vl4[4];
                const uint32_t off =
                    (uint32_t)((ks * 16 + vt_k) * KSTR + np * 16 + vt_n) * 2;
                ldsm4t(vh4, sVh_u + off);
                ldsm4t(vl4, sVl_u + off);
                mma16816(O[np * 2],     ph[ks], &vh4[0]);
                mma16816(O[np * 2 + 1], ph[ks], &vh4[2]);
                mma16816(O[np * 2],     pl[ks], &vh4[0]);
                mma16816(O[np * 2 + 1], pl[ks], &vh4[2]);
                mma16816(O[np * 2],     ph[ks], &vl4[0]);
                mma16816(O[np * 2 + 1], ph[ks], &vl4[2]);
            }
        }
        __syncthreads();
        bufi ^= 1;
    }

    const float inv0 = 1.f / l0;
    const float inv1 = 1.f / l1;
    const size_t ob0 = (size_t)(b * TSEQ + r0g) * DM + h * HD;
    const size_t ob1 = (size_t)(b * TSEQ + r1g) * DM + h * HD;
#pragma unroll
    for (int nt = 0; nt < 8; nt++) {
        const float v0 = O[nt][0] * inv0, v1 = O[nt][1] * inv0;
        const float v2 = O[nt][2] * inv1, v3 = O[nt][3] * inv1;
        const __nv_bfloat16 h0 = __float2bfloat16(v0);
        const __nv_bfloat16 h1 = __float2bfloat16(v1);
        const __nv_bfloat16 h2 = __float2bfloat16(v2);
        const __nv_bfloat16 h3 = __float2bfloat16(v3);
        __nv_bfloat162 t01 = __halves2bfloat162(h0, h1);
        __nv_bfloat162 t23 = __halves2bfloat162(h2, h3);
        *(uint32_t*)&g_ah[ob0 + nt * 8 + qcol] = *(uint32_t*)&t01;
        *(uint32_t*)&g_ah[ob1 + nt * 8 + qcol] = *(uint32_t*)&t23;
        *(uint32_t*)&g_al[ob0 + nt * 8 + qcol] =
            packbf(v0 - __bfloat162float(h0), v1 - __bfloat162float(h1));
        *(uint32_t*)&g_al[ob1 + nt * 8 + qcol] =
            packbf(v2 - __bfloat162float(h2), v3 - __bfloat162float(h3));
    }
}

// ---------------------------------------------------------------------------
extern "C" void kernel_launch(void* const* d_in, const int* in_sizes, int n_in,
                              void* d_out, int out_size)
{
    const float* x  = (const float*)d_in[0];
    const float* Wq = (const float*)d_in[1];
    const float* Wk = (const float*)d_in[2];
    const float* Wv = (const float*)d_in[3];
    const float* Wo = (const float*)d_in[4];
    float* out = (float*)d_out;

    cudaFuncSetAttribute(tgemm_kernel,
                         cudaFuncAttributeMaxDynamicSharedMemorySize, GSMEM_BYTES);
    cudaFuncSetAttribute(attn_kernel,
                         cudaFuncAttributeMaxDynamicSharedMemorySize, ATT_SMEM);

    const int total4 = XN4 + 4 * WN4;
    split_all<<<(total4 + 255) / 256, 256>>>(x, Wq, Wk, Wv, Wo);

    dim3 gq(DM / 128, MR / 128, 3);
    tgemm_kernel<<<gq, 256, GSMEM_BYTES>>>(0, nullptr);

    dim3 ga(TSEQ / 128, NH, BB);
    attn_kernel<<<ga, 256, ATT_SMEM>>>();

    dim3 gp(DM / 128, MR / 128, 1);
    tgemm_kernel<<<gp, 256, GSMEM_BYTES>>>(3, out);
}